// round 7
// baseline (speedup 1.0000x reference)
#include <cuda_runtime.h>
#include <math.h>

#define NTOK 49
#define DIM  96
#define QKVC 288

// ---- shared memory plan (floats) ----
constexpr int QS_STRIDE = 196;                 // rows 56: cols 0..95 Q->O, 96..191 K
constexpr int QS_SIZE   = 56 * QS_STRIDE;      // 10976
constexpr int AT_STRIDE = 60;                  // P [176][60]; also x tile [49][100]
constexpr int AT_ROWS   = 176;
constexpr int XA_SIZE   = AT_ROWS * AT_STRIDE; // 10560
constexpr int VT_STRIDE = 60;                  // V^T [96][60] (col=token, padded 0)
constexpr int VT_SIZE   = 96 * VT_STRIDE;      // 5760
constexpr int XS_STRIDE = 100;
constexpr int SMEM_FLOATS = QS_SIZE + XA_SIZE + VT_SIZE;   // 27296
constexpr int SMEM_BYTES  = SMEM_FLOATS * 4;               // 109184 -> 2 CTAs/SM

// ---- precomputed weights (tf32, fragment-paired) + fused bias ----
__device__ float2 g_wq[12 * QKVC * 4];
__device__ float2 g_wp[12 * DIM * 4];
__device__ float  g_bias[3 * 64 * 56];

__device__ __forceinline__ unsigned f2tf(float f) {
    unsigned r; asm("cvt.rna.tf32.f32 %0, %1;" : "=r"(r) : "f"(f)); return r;
}
__device__ __forceinline__ float tf32f(float f) { return __uint_as_float(f2tf(f)); }

__device__ __forceinline__ void mma_tf32(float& c0, float& c1, float& c2, float& c3,
                                         unsigned a0, unsigned a1, unsigned a2, unsigned a3,
                                         unsigned b0, unsigned b1) {
    asm volatile("mma.sync.aligned.m16n8k8.row.col.f32.tf32.tf32.f32 "
                 "{%0,%1,%2,%3}, {%4,%5,%6,%7}, {%8,%9}, {%0,%1,%2,%3};"
                 : "+f"(c0), "+f"(c1), "+f"(c2), "+f"(c3)
                 : "r"(a0), "r"(a1), "r"(a2), "r"(a3), "r"(b0), "r"(b1));
}
__device__ __forceinline__ void ldsm_x4(unsigned& a0, unsigned& a1, unsigned& a2, unsigned& a3,
                                        unsigned addr) {
    asm volatile("ldmatrix.sync.aligned.m8n8.x4.shared.b16 {%0,%1,%2,%3}, [%4];"
                 : "=r"(a0), "=r"(a1), "=r"(a2), "=r"(a3) : "r"(addr));
}
__device__ __forceinline__ void ldsm_x2(unsigned& b0, unsigned& b1, unsigned addr) {
    asm volatile("ldmatrix.sync.aligned.m8n8.x2.shared.b16 {%0,%1}, [%2];"
                 : "=r"(b0), "=r"(b1) : "r"(addr));
}
__device__ __forceinline__ unsigned s2u(const void* p) {
    return (unsigned)__cvta_generic_to_shared(p);
}

__global__ void prep_kernel(const float* __restrict__ qkv_w, const float* __restrict__ proj_w,
                            const float* __restrict__ bias_table, const int* __restrict__ rel_index) {
    int i = blockIdx.x * 256 + threadIdx.x;
    if (i < 12 * QKVC * 4) {
        int kk = i / (QKVC * 4), rem = i % (QKVC * 4), c = rem >> 2, tg = rem & 3;
        g_wq[i] = make_float2(__uint_as_float(f2tf(qkv_w[(kk * 8 + tg) * QKVC + c])),
                              __uint_as_float(f2tf(qkv_w[(kk * 8 + tg + 4) * QKVC + c])));
    }
    if (i < 12 * DIM * 4) {
        int kk = i / (DIM * 4), rem = i % (DIM * 4), c = rem >> 2, tg = rem & 3;
        g_wp[i] = make_float2(__uint_as_float(f2tf(proj_w[(kk * 8 + tg) * DIM + c])),
                              __uint_as_float(f2tf(proj_w[(kk * 8 + tg + 4) * DIM + c])));
    }
    if (i < 3 * 64 * 56) {
        int h = i / (64 * 56), rem = i % (64 * 56), m = rem / 56, n = rem % 56;
        g_bias[i] = (m < NTOK && n < NTOK) ? bias_table[rel_index[m * NTOK + n] * 3 + h] : 0.f;
    }
}

__global__ void __launch_bounds__(384, 2)
win_attn_kernel(const float* __restrict__ x,
                const float* __restrict__ qkv_b,
                const float* __restrict__ proj_b,
                float*       __restrict__ out)
{
    extern __shared__ float sm[];
    float* qs = sm;                 // [56][196]
    float* xa = sm + QS_SIZE;       // x tile [49][100] then P [176][60]
    float* vt = xa + XA_SIZE;       // V^T [96][60]

    const int b    = blockIdx.x;
    const int tid  = threadIdx.x;
    const int warp = tid >> 5;           // 0..11
    const int lane = tid & 31;
    const int g    = lane >> 2;
    const int tg   = lane & 3;
    const int rl   = lane & 7;
    const int sel  = lane >> 3;
    const int sel2 = sel & 1;
    const float NEGINF = __int_as_float(0xff800000);

    const unsigned qs_u = s2u(qs);
    const unsigned xa_u = s2u(xa);
    const unsigned vt_u = s2u(vt);

    const int rowA = (sel & 1) << 3;          // ldsm A row offset
    const int colA = (sel >> 1) << 2;         // ldsm A col offset (floats)
    const int colBp = ((sel & 1) << 2) + ((sel >> 1) << 3);  // paired-B col offset

    // ---- stage 0: load x (tf32-rounded) -> xa; zero V^T token pad cols ----
    const float* xg = x + (size_t)b * (NTOK * DIM);
    for (int i = tid; i < NTOK * DIM / 4; i += 384) {
        int n = i / (DIM / 4), k4 = i % (DIM / 4);
        float4 v = ((const float4*)xg)[i];
        float* d = &xa[n * XS_STRIDE + 4 * k4];
        d[0] = tf32f(v.x); d[1] = tf32f(v.y); d[2] = tf32f(v.z); d[3] = tf32f(v.w);
    }
    for (int i = tid; i < 96 * 11; i += 384) {
        int r = i / 11, c = 49 + i % 11;
        vt[r * VT_STRIDE + c] = 0.f;
    }
    __syncthreads();

    // ---- stage 1: qkv = x @ Wqkv + b. 12 jobs = (mt 0..3) x (cg: Q/K/V group of 96) ----
    {
        const int mt = warp & 3, cg = warp >> 2;
        const int m0 = mt * 16;
        const int rA = m0 + g, rB = rA + 8;
        const float sc = (cg == 0) ? 0.17677669529663687f : 1.0f;

        #pragma unroll 1
        for (int half = 0; half < 2; half++) {
            const int cbase = cg * 96 + half * 48;
            float acc[6][4];
            #pragma unroll
            for (int ni = 0; ni < 6; ni++)
                #pragma unroll
                for (int j = 0; j < 4; j++) acc[ni][j] = 0.f;

            unsigned aaddr = xa_u + (((m0 + rl + rowA) * XS_STRIDE + colA) << 2);
            float2 Bc[6];
            #pragma unroll
            for (int ni = 0; ni < 6; ni++)
                Bc[ni] = g_wq[(cbase + ni * 8 + g) * 4 + tg];

            #pragma unroll 1
            for (int kk = 0; kk < 12; kk++) {
                unsigned A0, A1, A2, A3;
                ldsm_x4(A0, A1, A2, A3, aaddr); aaddr += 32;
                float2 Bn[6];
                if (kk < 11) {
                    #pragma unroll
                    for (int ni = 0; ni < 6; ni++)
                        Bn[ni] = g_wq[((kk + 1) * QKVC + cbase + ni * 8 + g) * 4 + tg];
                }
                #pragma unroll
                for (int ni = 0; ni < 6; ni++)
                    mma_tf32(acc[ni][0], acc[ni][1], acc[ni][2], acc[ni][3],
                             A0, A1, A2, A3,
                             __float_as_uint(Bc[ni].x), __float_as_uint(Bc[ni].y));
                #pragma unroll
                for (int ni = 0; ni < 6; ni++) Bc[ni] = Bn[ni];
            }

            #pragma unroll
            for (int ni = 0; ni < 6; ni++) {
                int cl = half * 48 + ni * 8 + tg * 2;      // local col within group
                float2 bb = *(const float2*)&qkv_b[cg * 96 + cl];
                float v0 = tf32f((acc[ni][0] + bb.x) * sc);
                float v1 = tf32f((acc[ni][1] + bb.y) * sc);
                float v2 = tf32f((acc[ni][2] + bb.x) * sc);
                float v3 = tf32f((acc[ni][3] + bb.y) * sc);
                if (cg < 2) {
                    int col = cg * 96 + cl;                // Q at 0..95, K at 96..191
                    if (rA < NTOK) *(float2*)&qs[rA * QS_STRIDE + col] = make_float2(v0, v1);
                    if (rB < NTOK) *(float2*)&qs[rB * QS_STRIDE + col] = make_float2(v2, v3);
                } else {
                    if (rA < NTOK) { vt[cl * VT_STRIDE + rA] = v0; vt[(cl + 1) * VT_STRIDE + rA] = v1; }
                    if (rB < NTOK) { vt[cl * VT_STRIDE + rB] = v2; vt[(cl + 1) * VT_STRIDE + rB] = v3; }
                }
            }
        }
    }
    __syncthreads();

    // ---- stages 2-4 fused: 12 jobs = (h, mt), one per warp ----
    {
        const int h = warp >> 2, mt = warp & 3, m0 = mt * 16;
        const int rA = m0 + g, rB = rA + 8;

        // logits = Qs @ K^T  (paired-k ldsm.x4 for K)
        float a[7][4];
        #pragma unroll
        for (int nt = 0; nt < 7; nt++)
            #pragma unroll
            for (int j = 0; j < 4; j++) a[nt][j] = 0.f;

        unsigned qaddr = qs_u + (((m0 + rl + rowA) * QS_STRIDE + h * 32 + colA) << 2);
        const int kcol = 96 + h * 32 + colBp;

        #pragma unroll
        for (int ksp = 0; ksp < 2; ksp++) {
            unsigned A0, A1, A2, A3, A4, A5, A6, A7;
            ldsm_x4(A0, A1, A2, A3, qaddr); qaddr += 32;
            ldsm_x4(A4, A5, A6, A7, qaddr); qaddr += 32;
            #pragma unroll
            for (int nt = 0; nt < 7; nt++) {
                unsigned kaddr = qs_u + (((nt * 8 + rl) * QS_STRIDE + kcol + ksp * 16) << 2);
                unsigned b0, b1, b2, b3;
                ldsm_x4(b0, b1, b2, b3, kaddr);
                mma_tf32(a[nt][0], a[nt][1], a[nt][2], a[nt][3], A0, A1, A2, A3, b0, b1);
                mma_tf32(a[nt][0], a[nt][1], a[nt][2], a[nt][3], A4, A5, A6, A7, b2, b3);
            }
        }

        // + fused bias, -inf mask on pad cols
        #pragma unroll
        for (int nt = 0; nt < 7; nt++) {
            int n0p = nt * 8 + tg * 2;
            float2 bA = *(const float2*)&g_bias[(h * 64 + rA) * 56 + n0p];
            float2 bB = *(const float2*)&g_bias[(h * 64 + rB) * 56 + n0p];
            a[nt][0] = (n0p     < NTOK) ? a[nt][0] + bA.x : NEGINF;
            a[nt][1] = (n0p + 1 < NTOK) ? a[nt][1] + bA.y : NEGINF;
            a[nt][2] = (n0p     < NTOK) ? a[nt][2] + bB.x : NEGINF;
            a[nt][3] = (n0p + 1 < NTOK) ? a[nt][3] + bB.y : NEGINF;
        }

        // register softmax
        float mA = NEGINF, mB = NEGINF;
        #pragma unroll
        for (int nt = 0; nt < 7; nt++) {
            mA = fmaxf(mA, fmaxf(a[nt][0], a[nt][1]));
            mB = fmaxf(mB, fmaxf(a[nt][2], a[nt][3]));
        }
        mA = fmaxf(mA, __shfl_xor_sync(0xffffffffu, mA, 1));
        mA = fmaxf(mA, __shfl_xor_sync(0xffffffffu, mA, 2));
        mB = fmaxf(mB, __shfl_xor_sync(0xffffffffu, mB, 1));
        mB = fmaxf(mB, __shfl_xor_sync(0xffffffffu, mB, 2));
        float sA = 0.f, sB = 0.f;
        #pragma unroll
        for (int nt = 0; nt < 7; nt++) {
            a[nt][0] = __expf(a[nt][0] - mA);
            a[nt][1] = __expf(a[nt][1] - mA);
            a[nt][2] = __expf(a[nt][2] - mB);
            a[nt][3] = __expf(a[nt][3] - mB);
            sA += a[nt][0] + a[nt][1];
            sB += a[nt][2] + a[nt][3];
        }
        sA += __shfl_xor_sync(0xffffffffu, sA, 1);
        sA += __shfl_xor_sync(0xffffffffu, sA, 2);
        sB += __shfl_xor_sync(0xffffffffu, sB, 1);
        sB += __shfl_xor_sync(0xffffffffu, sB, 2);
        float iA = 1.0f / sA, iB = 1.0f / sB;

        // store P (tf32); pad cols exact 0
        #pragma unroll
        for (int nt = 0; nt < 7; nt++) {
            int n0p = nt * 8 + tg * 2;
            if (rA < NTOK)
                *(float2*)&xa[(h * 56 + rA) * AT_STRIDE + n0p] =
                    make_float2(tf32f(a[nt][0] * iA), tf32f(a[nt][1] * iA));
            if (rB < NTOK)
                *(float2*)&xa[(h * 56 + rB) * AT_STRIDE + n0p] =
                    make_float2(tf32f(a[nt][2] * iB), tf32f(a[nt][3] * iB));
        }
        __syncwarp();

        // O = P @ V^T  (K padded to 56; paired-k ldsm.x4 for V)
        float o[4][4];
        #pragma unroll
        for (int nt = 0; nt < 4; nt++)
            #pragma unroll
            for (int j = 0; j < 4; j++) o[nt][j] = 0.f;

        unsigned paddr = xa_u + (((h * 56 + m0 + rl + rowA) * AT_STRIDE + colA) << 2);
        const int vrow = h * 32;

        #pragma unroll
        for (int ksp = 0; ksp < 3; ksp++) {
            unsigned A0, A1, A2, A3, A4, A5, A6, A7;
            ldsm_x4(A0, A1, A2, A3, paddr); paddr += 32;
            ldsm_x4(A4, A5, A6, A7, paddr); paddr += 32;
            #pragma unroll
            for (int nt = 0; nt < 4; nt++) {
                unsigned vaddr = vt_u + (((vrow + nt * 8 + rl) * VT_STRIDE + ksp * 16 + colBp) << 2);
                unsigned b0, b1, b2, b3;
                ldsm_x4(b0, b1, b2, b3, vaddr);
                mma_tf32(o[nt][0], o[nt][1], o[nt][2], o[nt][3], A0, A1, A2, A3, b0, b1);
                mma_tf32(o[nt][0], o[nt][1], o[nt][2], o[nt][3], A4, A5, A6, A7, b2, b3);
            }
        }
        {   // final k-step (ks = 6, cols 48..55)
            unsigned A0, A1, A2, A3;
            ldsm_x4(A0, A1, A2, A3, paddr);
            #pragma unroll
            for (int nt = 0; nt < 4; nt++) {
                unsigned vaddr = vt_u + (((vrow + nt * 8 + rl) * VT_STRIDE + 48 + (sel2 << 2)) << 2);
                unsigned b0, b1;
                ldsm_x2(b0, b1, vaddr);
                mma_tf32(o[nt][0], o[nt][1], o[nt][2], o[nt][3], A0, A1, A2, A3, b0, b1);
            }
        }
        #pragma unroll
        for (int nt = 0; nt < 4; nt++) {
            int col = h * 32 + nt * 8 + tg * 2;
            if (rA < NTOK) *(float2*)&qs[rA * QS_STRIDE + col] =
                make_float2(tf32f(o[nt][0]), tf32f(o[nt][1]));
            if (rB < NTOK) *(float2*)&qs[rB * QS_STRIDE + col] =
                make_float2(tf32f(o[nt][2]), tf32f(o[nt][3]));
        }
    }
    __syncthreads();

    // ---- stage 5: out = O @ Wproj + b. 12 jobs = (mt) x (cg of 32 cols) ----
    {
        const int mt = warp & 3, cg = warp >> 2;
        const int m0 = mt * 16, nc0 = cg * 32;
        const int rA = m0 + g, rB = rA + 8;

        float acc[4][4];
        #pragma unroll
        for (int ni = 0; ni < 4; ni++)
            #pragma unroll
            for (int j = 0; j < 4; j++) acc[ni][j] = 0.f;

        unsigned aaddr = qs_u + (((m0 + rl + rowA) * QS_STRIDE + colA) << 2);
        float2 Bc[4];
        #pragma unroll
        for (int ni = 0; ni < 4; ni++)
            Bc[ni] = g_wp[(nc0 + ni * 8 + g) * 4 + tg];

        #pragma unroll 1
        for (int kk = 0; kk < 12; kk++) {
            unsigned A0, A1, A2, A3;
            ldsm_x4(A0, A1, A2, A3, aaddr); aaddr += 32;
            float2 Bn[4];
            if (kk < 11) {
                #pragma unroll
                for (int ni = 0; ni < 4; ni++)
                    Bn[ni] = g_wp[((kk + 1) * DIM + nc0 + ni * 8 + g) * 4 + tg];
            }
            #pragma unroll
            for (int ni = 0; ni < 4; ni++)
                mma_tf32(acc[ni][0], acc[ni][1], acc[ni][2], acc[ni][3],
                         A0, A1, A2, A3,
                         __float_as_uint(Bc[ni].x), __float_as_uint(Bc[ni].y));
            #pragma unroll
            for (int ni = 0; ni < 4; ni++) Bc[ni] = Bn[ni];
        }

        float* og = out + (size_t)b * (NTOK * DIM);
        #pragma unroll
        for (int ni = 0; ni < 4; ni++) {
            int n = nc0 + ni * 8 + tg * 2;
            float2 pb = *(const float2*)&proj_b[n];
            if (rA < NTOK) *(float2*)&og[rA * DIM + n] =
                make_float2(acc[ni][0] + pb.x, acc[ni][1] + pb.y);
            if (rB < NTOK) *(float2*)&og[rB * DIM + n] =
                make_float2(acc[ni][2] + pb.x, acc[ni][3] + pb.y);
        }
    }
}

extern "C" void kernel_launch(void* const* d_in, const int* in_sizes, int n_in,
                              void* d_out, int out_size)
{
    const float* x          = (const float*)d_in[0];
    const float* qkv_w      = (const float*)d_in[2];
    const float* qkv_b      = (const float*)d_in[3];
    const float* proj_w     = (const float*)d_in[4];
    const float* proj_b     = (const float*)d_in[5];
    const float* bias_table = (const float*)d_in[6];
    const int*   rel_index  = (const int*)d_in[7];
    float* out = (float*)d_out;

    int nwin = in_sizes[0] / (NTOK * DIM);

    prep_kernel<<<54, 256>>>(qkv_w, proj_w, bias_table, rel_index);

    cudaFuncSetAttribute(win_attn_kernel,
                         cudaFuncAttributeMaxDynamicSharedMemorySize, SMEM_BYTES);
    win_attn_kernel<<<nwin, 384, SMEM_BYTES>>>(x, qkv_b, proj_b, out);
    (void)n_in; (void)out_size;
}

// round 8
// speedup vs baseline: 1.2964x; 1.2964x over previous
#include <cuda_runtime.h>
#include <math.h>

#define NTOK 49
#define DIM  96
#define QKVC 288

// ---- shared memory plan (floats) ----
constexpr int QS_STRIDE = 196;                 // rows 56: cols 0..95 Q->O, 96..191 K
constexpr int QS_SIZE   = 56 * QS_STRIDE;      // 10976
constexpr int AT_STRIDE = 60;                  // P [176][60]; also x tile [49][100]
constexpr int AT_ROWS   = 176;
constexpr int XA_SIZE   = AT_ROWS * AT_STRIDE; // 10560
constexpr int VT_STRIDE = 60;                  // V^T [96][60] (col=token, padded 0)
constexpr int VT_SIZE   = 96 * VT_STRIDE;      // 5760
constexpr int XS_STRIDE = 100;
constexpr int SMEM_FLOATS = QS_SIZE + XA_SIZE + VT_SIZE;   // 27296
constexpr int SMEM_BYTES  = SMEM_FLOATS * 4;               // 109184 -> 2 CTAs/SM

// ---- precomputed weights (tf32, fragment-paired) + fused bias ----
__device__ float2 g_wq[12 * QKVC * 4];
__device__ float2 g_wp[12 * DIM * 4];
__device__ float  g_bias[3 * 64 * 56];

__device__ __forceinline__ unsigned f2tf(float f) {
    unsigned r; asm("cvt.rna.tf32.f32 %0, %1;" : "=r"(r) : "f"(f)); return r;
}
__device__ __forceinline__ float tf32f(float f) { return __uint_as_float(f2tf(f)); }

__device__ __forceinline__ void mma_tf32(float& c0, float& c1, float& c2, float& c3,
                                         unsigned a0, unsigned a1, unsigned a2, unsigned a3,
                                         unsigned b0, unsigned b1) {
    asm volatile("mma.sync.aligned.m16n8k8.row.col.f32.tf32.tf32.f32 "
                 "{%0,%1,%2,%3}, {%4,%5,%6,%7}, {%8,%9}, {%0,%1,%2,%3};"
                 : "+f"(c0), "+f"(c1), "+f"(c2), "+f"(c3)
                 : "r"(a0), "r"(a1), "r"(a2), "r"(a3), "r"(b0), "r"(b1));
}
__device__ __forceinline__ void ldsm_x4(unsigned& a0, unsigned& a1, unsigned& a2, unsigned& a3,
                                        unsigned addr) {
    asm volatile("ldmatrix.sync.aligned.m8n8.x4.shared.b16 {%0,%1,%2,%3}, [%4];"
                 : "=r"(a0), "=r"(a1), "=r"(a2), "=r"(a3) : "r"(addr));
}
__device__ __forceinline__ void ldsm_x2(unsigned& b0, unsigned& b1, unsigned addr) {
    asm volatile("ldmatrix.sync.aligned.m8n8.x2.shared.b16 {%0,%1}, [%2];"
                 : "=r"(b0), "=r"(b1) : "r"(addr));
}
__device__ __forceinline__ unsigned s2u(const void* p) {
    return (unsigned)__cvta_generic_to_shared(p);
}

__global__ void prep_kernel(const float* __restrict__ qkv_w, const float* __restrict__ proj_w,
                            const float* __restrict__ bias_table, const int* __restrict__ rel_index) {
    int i = blockIdx.x * 256 + threadIdx.x;
    if (i < 12 * QKVC * 4) {
        int kk = i / (QKVC * 4), rem = i % (QKVC * 4), c = rem >> 2, tg = rem & 3;
        g_wq[i] = make_float2(__uint_as_float(f2tf(qkv_w[(kk * 8 + tg) * QKVC + c])),
                              __uint_as_float(f2tf(qkv_w[(kk * 8 + tg + 4) * QKVC + c])));
    }
    if (i < 12 * DIM * 4) {
        int kk = i / (DIM * 4), rem = i % (DIM * 4), c = rem >> 2, tg = rem & 3;
        g_wp[i] = make_float2(__uint_as_float(f2tf(proj_w[(kk * 8 + tg) * DIM + c])),
                              __uint_as_float(f2tf(proj_w[(kk * 8 + tg + 4) * DIM + c])));
    }
    if (i < 3 * 64 * 56) {
        int h = i / (64 * 56), rem = i % (64 * 56), m = rem / 56, n = rem % 56;
        g_bias[i] = (m < NTOK && n < NTOK) ? bias_table[rel_index[m * NTOK + n] * 3 + h] : 0.f;
    }
}

__global__ void __launch_bounds__(384, 2)
win_attn_kernel(const float* __restrict__ x,
                const float* __restrict__ qkv_b,
                const float* __restrict__ proj_b,
                float*       __restrict__ out)
{
    extern __shared__ float sm[];
    float* qs = sm;                 // [56][196]
    float* xa = sm + QS_SIZE;       // x tile [49][100] then P [176][60]
    float* vt = xa + XA_SIZE;       // V^T [96][60]

    const int b    = blockIdx.x;
    const int tid  = threadIdx.x;
    const int warp = tid >> 5;           // 0..11
    const int lane = tid & 31;
    const int g    = lane >> 2;
    const int tg   = lane & 3;
    const int rl   = lane & 7;
    const int sel  = lane >> 3;
    const int sel2 = sel & 1;
    const float NEGINF = __int_as_float(0xff800000);

    const unsigned qs_u = s2u(qs);
    const unsigned xa_u = s2u(xa);
    const unsigned vt_u = s2u(vt);

    const int rowA = (sel & 1) << 3;          // ldsm A row offset
    const int colA = (sel >> 1) << 2;         // ldsm A col offset (floats)
    const int colBp = ((sel & 1) << 2) + ((sel >> 1) << 3);  // paired-B col offset

    // ---- stage 0: load x (tf32-rounded) -> xa; zero V^T token pad cols ----
    const float* xg = x + (size_t)b * (NTOK * DIM);
    for (int i = tid; i < NTOK * DIM / 4; i += 384) {
        int n = i / (DIM / 4), k4 = i % (DIM / 4);
        float4 v = ((const float4*)xg)[i];
        float* d = &xa[n * XS_STRIDE + 4 * k4];
        d[0] = tf32f(v.x); d[1] = tf32f(v.y); d[2] = tf32f(v.z); d[3] = tf32f(v.w);
    }
    for (int i = tid; i < 96 * 11; i += 384) {
        int r = i / 11, c = 49 + i % 11;
        vt[r * VT_STRIDE + c] = 0.f;
    }
    __syncthreads();

    // ---- stage 1: qkv = x @ Wqkv + b. 12 warps x (4 m-tiles x 24 cols) ----
    {
        const int cbase = warp * 24;          // warp's 24 output cols (within one of Q/K/V)
        const int group = warp >> 2;          // 0=Q, 1=K, 2=V
        const float sc = (group == 0) ? 0.17677669529663687f : 1.0f;

        unsigned aaddr[4];
        #pragma unroll
        for (int mt = 0; mt < 4; mt++)
            aaddr[mt] = xa_u + (((mt * 16 + rl + rowA) * XS_STRIDE + colA) << 2);

        float acc[4][3][4];
        #pragma unroll
        for (int mt = 0; mt < 4; mt++)
            #pragma unroll
            for (int ni = 0; ni < 3; ni++)
                #pragma unroll
                for (int j = 0; j < 4; j++) acc[mt][ni][j] = 0.f;

        float2 Bc[3];
        #pragma unroll
        for (int ni = 0; ni < 3; ni++)
            Bc[ni] = g_wq[(cbase + ni * 8 + g) * 4 + tg];

        #pragma unroll 1
        for (int kk = 0; kk < 12; kk++) {
            unsigned A[4][4];
            #pragma unroll
            for (int mt = 0; mt < 4; mt++) {
                ldsm_x4(A[mt][0], A[mt][1], A[mt][2], A[mt][3], aaddr[mt]);
                aaddr[mt] += 32;
            }
            float2 Bn[3];
            if (kk < 11) {
                #pragma unroll
                for (int ni = 0; ni < 3; ni++)
                    Bn[ni] = g_wq[((kk + 1) * QKVC + cbase + ni * 8 + g) * 4 + tg];
            }
            #pragma unroll
            for (int mt = 0; mt < 4; mt++)
                #pragma unroll
                for (int ni = 0; ni < 3; ni++)
                    mma_tf32(acc[mt][ni][0], acc[mt][ni][1], acc[mt][ni][2], acc[mt][ni][3],
                             A[mt][0], A[mt][1], A[mt][2], A[mt][3],
                             __float_as_uint(Bc[ni].x), __float_as_uint(Bc[ni].y));
            #pragma unroll
            for (int ni = 0; ni < 3; ni++) Bc[ni] = Bn[ni];
        }

        float2 qb[3];
        #pragma unroll
        for (int ni = 0; ni < 3; ni++)
            qb[ni] = *(const float2*)&qkv_b[cbase + ni * 8 + tg * 2];

        #pragma unroll
        for (int mt = 0; mt < 4; mt++) {
            int rA = mt * 16 + g, rB = rA + 8;
            #pragma unroll
            for (int ni = 0; ni < 3; ni++) {
                int col = cbase + ni * 8 + tg * 2;          // global col 0..287
                float v0 = tf32f((acc[mt][ni][0] + qb[ni].x) * sc);
                float v1 = tf32f((acc[mt][ni][1] + qb[ni].y) * sc);
                float v2 = tf32f((acc[mt][ni][2] + qb[ni].x) * sc);
                float v3 = tf32f((acc[mt][ni][3] + qb[ni].y) * sc);
                if (group < 2) {
                    // Q cols 0..95 and K cols 96..191 map directly into qs
                    if (rA < NTOK) *(float2*)&qs[rA * QS_STRIDE + col] = make_float2(v0, v1);
                    if (rB < NTOK) *(float2*)&qs[rB * QS_STRIDE + col] = make_float2(v2, v3);
                } else {
                    int cl = col - 192;                     // V col -> vt row
                    if (rA < NTOK) { vt[cl * VT_STRIDE + rA] = v0; vt[(cl + 1) * VT_STRIDE + rA] = v1; }
                    if (rB < NTOK) { vt[cl * VT_STRIDE + rB] = v2; vt[(cl + 1) * VT_STRIDE + rB] = v3; }
                }
            }
        }
    }
    __syncthreads();

    // ---- stages 2-4 fused: 12 jobs = (h, mt), one per warp ----
    {
        const int h = warp >> 2, mt = warp & 3, m0 = mt * 16;
        const int rA = m0 + g, rB = rA + 8;

        // logits = Qs @ K^T  (paired-k ldsm.x4 for K)
        float a[7][4];
        #pragma unroll
        for (int nt = 0; nt < 7; nt++)
            #pragma unroll
            for (int j = 0; j < 4; j++) a[nt][j] = 0.f;

        unsigned qaddr = qs_u + (((m0 + rl + rowA) * QS_STRIDE + h * 32 + colA) << 2);
        const int kcol = 96 + h * 32 + colBp;

        #pragma unroll
        for (int ksp = 0; ksp < 2; ksp++) {
            unsigned A0, A1, A2, A3, A4, A5, A6, A7;
            ldsm_x4(A0, A1, A2, A3, qaddr); qaddr += 32;
            ldsm_x4(A4, A5, A6, A7, qaddr); qaddr += 32;
            #pragma unroll
            for (int nt = 0; nt < 7; nt++) {
                unsigned kaddr = qs_u + (((nt * 8 + rl) * QS_STRIDE + kcol + ksp * 16) << 2);
                unsigned b0, b1, b2, b3;
                ldsm_x4(b0, b1, b2, b3, kaddr);
                mma_tf32(a[nt][0], a[nt][1], a[nt][2], a[nt][3], A0, A1, A2, A3, b0, b1);
                mma_tf32(a[nt][0], a[nt][1], a[nt][2], a[nt][3], A4, A5, A6, A7, b2, b3);
            }
        }

        // + fused bias, -inf mask on pad cols
        #pragma unroll
        for (int nt = 0; nt < 7; nt++) {
            int n0p = nt * 8 + tg * 2;
            float2 bA = *(const float2*)&g_bias[(h * 64 + rA) * 56 + n0p];
            float2 bB = *(const float2*)&g_bias[(h * 64 + rB) * 56 + n0p];
            a[nt][0] = (n0p     < NTOK) ? a[nt][0] + bA.x : NEGINF;
            a[nt][1] = (n0p + 1 < NTOK) ? a[nt][1] + bA.y : NEGINF;
            a[nt][2] = (n0p     < NTOK) ? a[nt][2] + bB.x : NEGINF;
            a[nt][3] = (n0p + 1 < NTOK) ? a[nt][3] + bB.y : NEGINF;
        }

        // register softmax
        float mA = NEGINF, mB = NEGINF;
        #pragma unroll
        for (int nt = 0; nt < 7; nt++) {
            mA = fmaxf(mA, fmaxf(a[nt][0], a[nt][1]));
            mB = fmaxf(mB, fmaxf(a[nt][2], a[nt][3]));
        }
        mA = fmaxf(mA, __shfl_xor_sync(0xffffffffu, mA, 1));
        mA = fmaxf(mA, __shfl_xor_sync(0xffffffffu, mA, 2));
        mB = fmaxf(mB, __shfl_xor_sync(0xffffffffu, mB, 1));
        mB = fmaxf(mB, __shfl_xor_sync(0xffffffffu, mB, 2));
        float sA = 0.f, sB = 0.f;
        #pragma unroll
        for (int nt = 0; nt < 7; nt++) {
            a[nt][0] = __expf(a[nt][0] - mA);
            a[nt][1] = __expf(a[nt][1] - mA);
            a[nt][2] = __expf(a[nt][2] - mB);
            a[nt][3] = __expf(a[nt][3] - mB);
            sA += a[nt][0] + a[nt][1];
            sB += a[nt][2] + a[nt][3];
        }
        sA += __shfl_xor_sync(0xffffffffu, sA, 1);
        sA += __shfl_xor_sync(0xffffffffu, sA, 2);
        sB += __shfl_xor_sync(0xffffffffu, sB, 1);
        sB += __shfl_xor_sync(0xffffffffu, sB, 2);
        float iA = 1.0f / sA, iB = 1.0f / sB;

        // store P (tf32); pad cols exact 0
        #pragma unroll
        for (int nt = 0; nt < 7; nt++) {
            int n0p = nt * 8 + tg * 2;
            if (rA < NTOK)
                *(float2*)&xa[(h * 56 + rA) * AT_STRIDE + n0p] =
                    make_float2(tf32f(a[nt][0] * iA), tf32f(a[nt][1] * iA));
            if (rB < NTOK)
                *(float2*)&xa[(h * 56 + rB) * AT_STRIDE + n0p] =
                    make_float2(tf32f(a[nt][2] * iB), tf32f(a[nt][3] * iB));
        }
        __syncwarp();

        // O = P @ V^T  (K padded to 56; paired-k ldsm.x4 for V)
        float o[4][4];
        #pragma unroll
        for (int nt = 0; nt < 4; nt++)
            #pragma unroll
            for (int j = 0; j < 4; j++) o[nt][j] = 0.f;

        unsigned paddr = xa_u + (((h * 56 + m0 + rl + rowA) * AT_STRIDE + colA) << 2);
        const int vrow = h * 32;

        #pragma unroll
        for (int ksp = 0; ksp < 3; ksp++) {
            unsigned A0, A1, A2, A3, A4, A5, A6, A7;
            ldsm_x4(A0, A1, A2, A3, paddr); paddr += 32;
            ldsm_x4(A4, A5, A6, A7, paddr); paddr += 32;
            #pragma unroll
            for (int nt = 0; nt < 4; nt++) {
                unsigned vaddr = vt_u + (((vrow + nt * 8 + rl) * VT_STRIDE + ksp * 16 + colBp) << 2);
                unsigned b0, b1, b2, b3;
                ldsm_x4(b0, b1, b2, b3, vaddr);
                mma_tf32(o[nt][0], o[nt][1], o[nt][2], o[nt][3], A0, A1, A2, A3, b0, b1);
                mma_tf32(o[nt][0], o[nt][1], o[nt][2], o[nt][3], A4, A5, A6, A7, b2, b3);
            }
        }
        {   // final k-step (ks = 6, cols 48..55)
            unsigned A0, A1, A2, A3;
            ldsm_x4(A0, A1, A2, A3, paddr);
            #pragma unroll
            for (int nt = 0; nt < 4; nt++) {
                unsigned vaddr = vt_u + (((vrow + nt * 8 + rl) * VT_STRIDE + 48 + (sel2 << 2)) << 2);
                unsigned b0, b1;
                ldsm_x2(b0, b1, vaddr);
                mma_tf32(o[nt][0], o[nt][1], o[nt][2], o[nt][3], A0, A1, A2, A3, b0, b1);
            }
        }
        #pragma unroll
        for (int nt = 0; nt < 4; nt++) {
            int col = h * 32 + nt * 8 + tg * 2;
            if (rA < NTOK) *(float2*)&qs[rA * QS_STRIDE + col] =
                make_float2(tf32f(o[nt][0]), tf32f(o[nt][1]));
            if (rB < NTOK) *(float2*)&qs[rB * QS_STRIDE + col] =
                make_float2(tf32f(o[nt][2]), tf32f(o[nt][3]));
        }
    }
    __syncthreads();

    // ---- stage 5: out = O @ Wproj + b. 12 jobs = (mt) x (cg of 32 cols) ----
    {
        const int mt = warp & 3, cg = warp >> 2;
        const int m0 = mt * 16, nc0 = cg * 32;
        const int rA = m0 + g, rB = rA + 8;

        float acc[4][4];
        #pragma unroll
        for (int ni = 0; ni < 4; ni++)
            #pragma unroll
            for (int j = 0; j < 4; j++) acc[ni][j] = 0.f;

        unsigned aaddr = qs_u + (((m0 + rl + rowA) * QS_STRIDE + colA) << 2);
        float2 Bc[4];
        #pragma unroll
        for (int ni = 0; ni < 4; ni++)
            Bc[ni] = g_wp[(nc0 + ni * 8 + g) * 4 + tg];

        #pragma unroll 1
        for (int kk = 0; kk < 12; kk++) {
            unsigned A0, A1, A2, A3;
            ldsm_x4(A0, A1, A2, A3, aaddr); aaddr += 32;
            float2 Bn[4];
            if (kk < 11) {
                #pragma unroll
                for (int ni = 0; ni < 4; ni++)
                    Bn[ni] = g_wp[((kk + 1) * DIM + nc0 + ni * 8 + g) * 4 + tg];
            }
            #pragma unroll
            for (int ni = 0; ni < 4; ni++)
                mma_tf32(acc[ni][0], acc[ni][1], acc[ni][2], acc[ni][3],
                         A0, A1, A2, A3,
                         __float_as_uint(Bc[ni].x), __float_as_uint(Bc[ni].y));
            #pragma unroll
            for (int ni = 0; ni < 4; ni++) Bc[ni] = Bn[ni];
        }

        float* og = out + (size_t)b * (NTOK * DIM);
        #pragma unroll
        for (int ni = 0; ni < 4; ni++) {
            int n = nc0 + ni * 8 + tg * 2;
            float2 pb = *(const float2*)&proj_b[n];
            if (rA < NTOK) *(float2*)&og[rA * DIM + n] =
                make_float2(acc[ni][0] + pb.x, acc[ni][1] + pb.y);
            if (rB < NTOK) *(float2*)&og[rB * DIM + n] =
                make_float2(acc[ni][2] + pb.x, acc[ni][3] + pb.y);
        }
    }
}

extern "C" void kernel_launch(void* const* d_in, const int* in_sizes, int n_in,
                              void* d_out, int out_size)
{
    const float* x          = (const float*)d_in[0];
    const float* qkv_w      = (const float*)d_in[2];
    const float* qkv_b      = (const float*)d_in[3];
    const float* proj_w     = (const float*)d_in[4];
    const float* proj_b     = (const float*)d_in[5];
    const float* bias_table = (const float*)d_in[6];
    const int*   rel_index  = (const int*)d_in[7];
    float* out = (float*)d_out;

    int nwin = in_sizes[0] / (NTOK * DIM);

    prep_kernel<<<54, 256>>>(qkv_w, proj_w, bias_table, rel_index);

    cudaFuncSetAttribute(win_attn_kernel,
                         cudaFuncAttributeMaxDynamicSharedMemorySize, SMEM_BYTES);
    win_attn_kernel<<<nwin, 384, SMEM_BYTES>>>(x, qkv_b, proj_b, out);
    (void)n_in; (void)out_size;
}

// round 9
// speedup vs baseline: 2.1426x; 1.6527x over previous
#include <cuda_runtime.h>
#include <cuda_fp16.h>
#include <math.h>

#define NTOK 49
#define DIM  96
#define QKVC 288

// ---- shared memory (halves) ----
constexpr int QKV_ST = 296;                    // qk rows 64: Q 0..95 | K 96..191 | V 192..287
constexpr int QKV_HALVES = 64 * QKV_ST;        // 18944
constexpr int XO_ST  = 104;                    // x tile then O, rows 64
constexpr int XO_HALVES = 64 * XO_ST;          // 6656
constexpr int SMEM_BYTES = (QKV_HALVES + XO_HALVES) * 2;   // 51200 -> 2 CTAs/SM

// ---- precomputed fp16 weights (B-fragment packed) + fused bias ----
__device__ uint2 g_wq[6 * QKVC * 4];   // [kk16][col][tg]: {W[16kk+2tg..+1][c], W[16kk+8+2tg..+1][c]}
__device__ uint2 g_wp[6 * DIM * 4];
__device__ float g_qb[QKVC];           // qkv bias (q-scaled)
__device__ float g_bias[3 * 64 * 56];  // fused relative-position bias

__device__ __forceinline__ unsigned pkh(float x, float y) {
    half2 h = __floats2half2_rn(x, y);
    return *(unsigned*)&h;
}
__device__ __forceinline__ void mma16(float& c0, float& c1, float& c2, float& c3,
                                      unsigned a0, unsigned a1, unsigned a2, unsigned a3,
                                      unsigned b0, unsigned b1) {
    asm volatile("mma.sync.aligned.m16n8k16.row.col.f32.f16.f16.f32 "
                 "{%0,%1,%2,%3}, {%4,%5,%6,%7}, {%8,%9}, {%0,%1,%2,%3};"
                 : "+f"(c0), "+f"(c1), "+f"(c2), "+f"(c3)
                 : "r"(a0), "r"(a1), "r"(a2), "r"(a3), "r"(b0), "r"(b1));
}
__device__ __forceinline__ void mma8(float& c0, float& c1, float& c2, float& c3,
                                     unsigned a0, unsigned a1, unsigned b0) {
    asm volatile("mma.sync.aligned.m16n8k8.row.col.f32.f16.f16.f32 "
                 "{%0,%1,%2,%3}, {%4,%5}, {%6}, {%0,%1,%2,%3};"
                 : "+f"(c0), "+f"(c1), "+f"(c2), "+f"(c3)
                 : "r"(a0), "r"(a1), "r"(b0));
}
__device__ __forceinline__ void ldsm_x4(unsigned& a0, unsigned& a1, unsigned& a2, unsigned& a3,
                                        unsigned addr) {
    asm volatile("ldmatrix.sync.aligned.m8n8.x4.shared.b16 {%0,%1,%2,%3}, [%4];"
                 : "=r"(a0), "=r"(a1), "=r"(a2), "=r"(a3) : "r"(addr));
}
__device__ __forceinline__ void ldsm_x4t(unsigned& a0, unsigned& a1, unsigned& a2, unsigned& a3,
                                         unsigned addr) {
    asm volatile("ldmatrix.sync.aligned.m8n8.x4.trans.shared.b16 {%0,%1,%2,%3}, [%4];"
                 : "=r"(a0), "=r"(a1), "=r"(a2), "=r"(a3) : "r"(addr));
}
__device__ __forceinline__ void ldsm_x2t(unsigned& b0, unsigned& b1, unsigned addr) {
    asm volatile("ldmatrix.sync.aligned.m8n8.x2.trans.shared.b16 {%0,%1}, [%2];"
                 : "=r"(b0), "=r"(b1) : "r"(addr));
}
__device__ __forceinline__ void ldsm_x1t(unsigned& b0, unsigned addr) {
    asm volatile("ldmatrix.sync.aligned.m8n8.x1.trans.shared.b16 {%0}, [%1];"
                 : "=r"(b0) : "r"(addr));
}
__device__ __forceinline__ unsigned s2u(const void* p) {
    return (unsigned)__cvta_generic_to_shared(p);
}

__global__ void prep_kernel(const float* __restrict__ qkv_w, const float* __restrict__ qkv_b,
                            const float* __restrict__ proj_w,
                            const float* __restrict__ bias_table, const int* __restrict__ rel_index) {
    const float SC = 0.17677669529663687f;
    int i = blockIdx.x * 256 + threadIdx.x;
    if (i < 6 * QKVC * 4) {
        int kk = i / (QKVC * 4), rem = i % (QKVC * 4), c = rem >> 2, tg = rem & 3;
        float s = (c < DIM) ? SC : 1.0f;
        int k0 = kk * 16 + 2 * tg;
        half2 lo = __floats2half2_rn(qkv_w[k0 * QKVC + c] * s, qkv_w[(k0 + 1) * QKVC + c] * s);
        half2 hi = __floats2half2_rn(qkv_w[(k0 + 8) * QKVC + c] * s, qkv_w[(k0 + 9) * QKVC + c] * s);
        g_wq[i] = make_uint2(*(unsigned*)&lo, *(unsigned*)&hi);
    }
    if (i < 6 * DIM * 4) {
        int kk = i / (DIM * 4), rem = i % (DIM * 4), c = rem >> 2, tg = rem & 3;
        int k0 = kk * 16 + 2 * tg;
        half2 lo = __floats2half2_rn(proj_w[k0 * DIM + c], proj_w[(k0 + 1) * DIM + c]);
        half2 hi = __floats2half2_rn(proj_w[(k0 + 8) * DIM + c], proj_w[(k0 + 9) * DIM + c]);
        g_wp[i] = make_uint2(*(unsigned*)&lo, *(unsigned*)&hi);
    }
    if (i < QKVC) g_qb[i] = qkv_b[i] * ((i < DIM) ? SC : 1.0f);
    if (i < 3 * 64 * 56) {
        int h = i / (64 * 56), rem = i % (64 * 56), m = rem / 56, n = rem % 56;
        g_bias[i] = (m < NTOK && n < NTOK) ? bias_table[rel_index[m * NTOK + n] * 3 + h] : 0.f;
    }
}

__global__ void __launch_bounds__(384, 2)
win_attn_kernel(const float* __restrict__ x,
                const float* __restrict__ proj_b,
                float*       __restrict__ out)
{
    extern __shared__ __half smh[];
    __half* qk = smh;                  // [64][296]
    __half* xo = smh + QKV_HALVES;     // [64][104] x tile, then O

    const int b    = blockIdx.x;
    const int tid  = threadIdx.x;
    const int warp = tid >> 5;           // 0..11
    const int lane = tid & 31;
    const int g    = lane >> 2;
    const int tg   = lane & 3;
    const int rl   = lane & 7;
    const int sel  = lane >> 3;
    const float NEGINF = __int_as_float(0xff800000);

    const unsigned qk_u = s2u(qk);
    const unsigned xo_u = s2u(xo);

    const int rowA  = (sel & 1) << 3;        // ldsm A row offset
    const int colAh = (sel >> 1) << 3;       // ldsm A col offset (halves)

    // ---- stage 0: x (fp16) -> xo; zero qk rows 49..63 ----
    const float* xg = x + (size_t)b * (NTOK * DIM);
    for (int i = tid; i < NTOK * DIM / 4; i += 384) {
        int n = i / (DIM / 4), k4 = i % (DIM / 4);
        float4 v = ((const float4*)xg)[i];
        __half* d = &xo[n * XO_ST + 4 * k4];
        *(half2*)d       = __floats2half2_rn(v.x, v.y);
        *(half2*)(d + 2) = __floats2half2_rn(v.z, v.w);
    }
    {   // zero pad rows of qk: 15 rows x 296 halves = 1110 uint2
        uint2* zp = (uint2*)&qk[49 * QKV_ST];
        for (int i = tid; i < 15 * QKV_ST / 4; i += 384) zp[i] = make_uint2(0u, 0u);
    }
    __syncthreads();

    // ---- stage 1: qkv = x @ Wqkv + b. 12 warps x (4 m-tiles x 24 cols) ----
    {
        const int cbase = warp * 24;

        unsigned aaddr[4];
        #pragma unroll
        for (int mt = 0; mt < 4; mt++)
            aaddr[mt] = xo_u + (((mt * 16 + rl + rowA) * XO_ST + colAh) << 1);

        float acc[4][3][4];
        #pragma unroll
        for (int mt = 0; mt < 4; mt++)
            #pragma unroll
            for (int ni = 0; ni < 3; ni++)
                #pragma unroll
                for (int j = 0; j < 4; j++) acc[mt][ni][j] = 0.f;

        uint2 Bc[3];
        #pragma unroll
        for (int ni = 0; ni < 3; ni++)
            Bc[ni] = g_wq[(cbase + ni * 8 + g) * 4 + tg];

        #pragma unroll 1
        for (int kk = 0; kk < 6; kk++) {
            unsigned A[4][4];
            #pragma unroll
            for (int mt = 0; mt < 4; mt++) {
                ldsm_x4(A[mt][0], A[mt][1], A[mt][2], A[mt][3], aaddr[mt]);
                aaddr[mt] += 32;          // +16 halves
            }
            uint2 Bn[3];
            if (kk < 5) {
                #pragma unroll
                for (int ni = 0; ni < 3; ni++)
                    Bn[ni] = g_wq[((kk + 1) * QKVC + cbase + ni * 8 + g) * 4 + tg];
            }
            #pragma unroll
            for (int mt = 0; mt < 4; mt++)
                #pragma unroll
                for (int ni = 0; ni < 3; ni++)
                    mma16(acc[mt][ni][0], acc[mt][ni][1], acc[mt][ni][2], acc[mt][ni][3],
                          A[mt][0], A[mt][1], A[mt][2], A[mt][3], Bc[ni].x, Bc[ni].y);
            #pragma unroll
            for (int ni = 0; ni < 3; ni++) Bc[ni] = Bn[ni];
        }

        #pragma unroll
        for (int ni = 0; ni < 3; ni++) {
            int col = cbase + ni * 8 + tg * 2;
            float2 bb = *(const float2*)&g_qb[col];
            #pragma unroll
            for (int mt = 0; mt < 4; mt++) {
                int rA = mt * 16 + g, rB = rA + 8;
                if (rA < NTOK) *(half2*)&qk[rA * QKV_ST + col] =
                    __floats2half2_rn(acc[mt][ni][0] + bb.x, acc[mt][ni][1] + bb.y);
                if (rB < NTOK) *(half2*)&qk[rB * QKV_ST + col] =
                    __floats2half2_rn(acc[mt][ni][2] + bb.x, acc[mt][ni][3] + bb.y);
            }
        }
    }
    __syncthreads();

    // ---- stages 2-4 fused: 12 jobs = (h, mt); P never touches smem ----
    {
        const int h = warp >> 2, mt = warp & 3, m0 = mt * 16;
        const int rA = m0 + g, rB = rA + 8;

        // S = Qs @ K^T
        float a[7][4];
        #pragma unroll
        for (int nt = 0; nt < 7; nt++)
            #pragma unroll
            for (int j = 0; j < 4; j++) a[nt][j] = 0.f;

        unsigned Aq[2][4];
        {
            unsigned qaddr = qk_u + (((m0 + rl + rowA) * QKV_ST + h * 32 + colAh) << 1);
            ldsm_x4(Aq[0][0], Aq[0][1], Aq[0][2], Aq[0][3], qaddr);
            ldsm_x4(Aq[1][0], Aq[1][1], Aq[1][2], Aq[1][3], qaddr + 32);
        }
        #pragma unroll
        for (int nt = 0; nt < 7; nt++) {
            unsigned kaddr = qk_u + (((nt * 8 + rl) * QKV_ST + 96 + h * 32 + (sel << 3)) << 1);
            unsigned b0, b1, b2, b3;
            ldsm_x4(b0, b1, b2, b3, kaddr);
            mma16(a[nt][0], a[nt][1], a[nt][2], a[nt][3],
                  Aq[0][0], Aq[0][1], Aq[0][2], Aq[0][3], b0, b1);
            mma16(a[nt][0], a[nt][1], a[nt][2], a[nt][3],
                  Aq[1][0], Aq[1][1], Aq[1][2], Aq[1][3], b2, b3);
        }

        // + bias, -inf mask on pad cols
        #pragma unroll
        for (int nt = 0; nt < 7; nt++) {
            int n0p = nt * 8 + tg * 2;
            float2 bA = *(const float2*)&g_bias[(h * 64 + rA) * 56 + n0p];
            float2 bB = *(const float2*)&g_bias[(h * 64 + rB) * 56 + n0p];
            a[nt][0] = (n0p     < NTOK) ? a[nt][0] + bA.x : NEGINF;
            a[nt][1] = (n0p + 1 < NTOK) ? a[nt][1] + bA.y : NEGINF;
            a[nt][2] = (n0p     < NTOK) ? a[nt][2] + bB.x : NEGINF;
            a[nt][3] = (n0p + 1 < NTOK) ? a[nt][3] + bB.y : NEGINF;
        }

        // register softmax
        float mA = NEGINF, mB = NEGINF;
        #pragma unroll
        for (int nt = 0; nt < 7; nt++) {
            mA = fmaxf(mA, fmaxf(a[nt][0], a[nt][1]));
            mB = fmaxf(mB, fmaxf(a[nt][2], a[nt][3]));
        }
        mA = fmaxf(mA, __shfl_xor_sync(0xffffffffu, mA, 1));
        mA = fmaxf(mA, __shfl_xor_sync(0xffffffffu, mA, 2));
        mB = fmaxf(mB, __shfl_xor_sync(0xffffffffu, mB, 1));
        mB = fmaxf(mB, __shfl_xor_sync(0xffffffffu, mB, 2));
        float sA = 0.f, sB = 0.f;
        #pragma unroll
        for (int nt = 0; nt < 7; nt++) {
            a[nt][0] = __expf(a[nt][0] - mA);
            a[nt][1] = __expf(a[nt][1] - mA);
            a[nt][2] = __expf(a[nt][2] - mB);
            a[nt][3] = __expf(a[nt][3] - mB);
            sA += a[nt][0] + a[nt][1];
            sB += a[nt][2] + a[nt][3];
        }
        sA += __shfl_xor_sync(0xffffffffu, sA, 1);
        sA += __shfl_xor_sync(0xffffffffu, sA, 2);
        sB += __shfl_xor_sync(0xffffffffu, sB, 1);
        sB += __shfl_xor_sync(0xffffffffu, sB, 2);
        float iA = 1.0f / sA, iB = 1.0f / sB;

        // pack P into fp16 A-fragments (C-frag layout == A-frag layout for f16 k16)
        unsigned pa[7][2];
        #pragma unroll
        for (int nt = 0; nt < 7; nt++) {
            pa[nt][0] = pkh(a[nt][0] * iA, a[nt][1] * iA);   // row g
            pa[nt][1] = pkh(a[nt][2] * iB, a[nt][3] * iB);   // row g+8
        }

        // O = P @ V  (V read as trans B-fragments from [token][dim])
        float o[4][4];
        #pragma unroll
        for (int nt = 0; nt < 4; nt++)
            #pragma unroll
            for (int j = 0; j < 4; j++) o[nt][j] = 0.f;

        #pragma unroll
        for (int nt = 0; nt < 4; nt++) {
            const int vcol = 192 + h * 32 + nt * 8;
            unsigned b0, b1, b2, b3, c0, c1, d0;
            ldsm_x4t(b0, b1, b2, b3, qk_u + (((rl + (sel << 3)) * QKV_ST + vcol) << 1));
            ldsm_x2t(c0, c1, qk_u + (((32 + rl + ((sel & 1) << 3)) * QKV_ST + vcol) << 1));
            ldsm_x1t(d0, qk_u + (((48 + rl) * QKV_ST + vcol) << 1));
            mma16(o[nt][0], o[nt][1], o[nt][2], o[nt][3],
                  pa[0][0], pa[0][1], pa[1][0], pa[1][1], b0, b1);
            mma16(o[nt][0], o[nt][1], o[nt][2], o[nt][3],
                  pa[2][0], pa[2][1], pa[3][0], pa[3][1], b2, b3);
            mma16(o[nt][0], o[nt][1], o[nt][2], o[nt][3],
                  pa[4][0], pa[4][1], pa[5][0], pa[5][1], c0, c1);
            mma8(o[nt][0], o[nt][1], o[nt][2], o[nt][3],
                 pa[6][0], pa[6][1], d0);
        }
        #pragma unroll
        for (int nt = 0; nt < 4; nt++) {
            int col = h * 32 + nt * 8 + tg * 2;
            if (rA < NTOK) *(half2*)&xo[rA * XO_ST + col] = __floats2half2_rn(o[nt][0], o[nt][1]);
            if (rB < NTOK) *(half2*)&xo[rB * XO_ST + col] = __floats2half2_rn(o[nt][2], o[nt][3]);
        }
    }
    __syncthreads();

    // ---- stage 5: out = O @ Wproj + b. 12 jobs = (mt) x (32-col group) ----
    {
        const int mt = warp & 3, cg = warp >> 2;
        const int m0 = mt * 16, nc0 = cg * 32;
        const int rA = m0 + g, rB = rA + 8;

        float acc[4][4];
        #pragma unroll
        for (int ni = 0; ni < 4; ni++)
            #pragma unroll
            for (int j = 0; j < 4; j++) acc[ni][j] = 0.f;

        unsigned aaddr = xo_u + (((m0 + rl + rowA) * XO_ST + colAh) << 1);
        uint2 Bc[4];
        #pragma unroll
        for (int ni = 0; ni < 4; ni++)
            Bc[ni] = g_wp[(nc0 + ni * 8 + g) * 4 + tg];

        #pragma unroll 1
        for (int kk = 0; kk < 6; kk++) {
            unsigned A0, A1, A2, A3;
            ldsm_x4(A0, A1, A2, A3, aaddr); aaddr += 32;
            uint2 Bn[4];
            if (kk < 5) {
                #pragma unroll
                for (int ni = 0; ni < 4; ni++)
                    Bn[ni] = g_wp[((kk + 1) * DIM + nc0 + ni * 8 + g) * 4 + tg];
            }
            #pragma unroll
            for (int ni = 0; ni < 4; ni++)
                mma16(acc[ni][0], acc[ni][1], acc[ni][2], acc[ni][3],
                      A0, A1, A2, A3, Bc[ni].x, Bc[ni].y);
            #pragma unroll
            for (int ni = 0; ni < 4; ni++) Bc[ni] = Bn[ni];
        }

        float* og = out + (size_t)b * (NTOK * DIM);
        #pragma unroll
        for (int ni = 0; ni < 4; ni++) {
            int n = nc0 + ni * 8 + tg * 2;
            float2 pb = *(const float2*)&proj_b[n];
            if (rA < NTOK) *(float2*)&og[rA * DIM + n] =
                make_float2(acc[ni][0] + pb.x, acc[ni][1] + pb.y);
            if (rB < NTOK) *(float2*)&og[rB * DIM + n] =
                make_float2(acc[ni][2] + pb.x, acc[ni][3] + pb.y);
        }
    }
}

extern "C" void kernel_launch(void* const* d_in, const int* in_sizes, int n_in,
                              void* d_out, int out_size)
{
    const float* x          = (const float*)d_in[0];
    const float* qkv_w      = (const float*)d_in[2];
    const float* qkv_b      = (const float*)d_in[3];
    const float* proj_w     = (const float*)d_in[4];
    const float* proj_b     = (const float*)d_in[5];
    const float* bias_table = (const float*)d_in[6];
    const int*   rel_index  = (const int*)d_in[7];
    float* out = (float*)d_out;

    int nwin = in_sizes[0] / (NTOK * DIM);

    prep_kernel<<<42, 256>>>(qkv_w, qkv_b, proj_w, bias_table, rel_index);

    cudaFuncSetAttribute(win_attn_kernel,
                         cudaFuncAttributeMaxDynamicSharedMemorySize, SMEM_BYTES);
    win_attn_kernel<<<nwin, 384, SMEM_BYTES>>>(x, proj_b, out);
    (void)n_in; (void)out_size;
}

// round 10
// speedup vs baseline: 2.1975x; 1.0256x over previous
#include <cuda_runtime.h>
#include <cuda_fp16.h>
#include <math.h>

#define NTOK 49
#define DIM  96
#define QKVC 288

// ---- shared memory (halves) ----
constexpr int QKV_ST = 296;                    // qk rows 64: Q 0..95 | K 96..191 | V 192..287
constexpr int QKV_HALVES = 64 * QKV_ST;        // 18944
constexpr int XO_ST  = 104;                    // x tile then O, rows 64
constexpr int XO_HALVES = 64 * XO_ST;          // 6656
constexpr int SMEM_BYTES = (QKV_HALVES + XO_HALVES) * 2;   // 51200 -> 2 CTAs/SM
constexpr int OS_ST = 104;                     // f32 output staging stride (aliases qk region)

// ---- precomputed fp16 weights (B-fragment packed) + fused bias (half2) ----
__device__ uint2 g_wq[6 * QKVC * 4];   // [kk16][col][tg]
__device__ uint2 g_wp[6 * DIM * 4];
__device__ float g_qb[QKVC];           // qkv bias (q-scaled)
__device__ unsigned g_biash[3 * 64 * 28];   // half2 pairs: [h][m][pair]

__device__ __forceinline__ unsigned pkh(float x, float y) {
    half2 h = __floats2half2_rn(x, y);
    return *(unsigned*)&h;
}
__device__ __forceinline__ float2 uph(unsigned u) {
    return __half22float2(*(half2*)&u);
}
__device__ __forceinline__ void mma16(float& c0, float& c1, float& c2, float& c3,
                                      unsigned a0, unsigned a1, unsigned a2, unsigned a3,
                                      unsigned b0, unsigned b1) {
    asm volatile("mma.sync.aligned.m16n8k16.row.col.f32.f16.f16.f32 "
                 "{%0,%1,%2,%3}, {%4,%5,%6,%7}, {%8,%9}, {%0,%1,%2,%3};"
                 : "+f"(c0), "+f"(c1), "+f"(c2), "+f"(c3)
                 : "r"(a0), "r"(a1), "r"(a2), "r"(a3), "r"(b0), "r"(b1));
}
__device__ __forceinline__ void mma8(float& c0, float& c1, float& c2, float& c3,
                                     unsigned a0, unsigned a1, unsigned b0) {
    asm volatile("mma.sync.aligned.m16n8k8.row.col.f32.f16.f16.f32 "
                 "{%0,%1,%2,%3}, {%4,%5}, {%6}, {%0,%1,%2,%3};"
                 : "+f"(c0), "+f"(c1), "+f"(c2), "+f"(c3)
                 : "r"(a0), "r"(a1), "r"(b0));
}
__device__ __forceinline__ void ldsm_x4(unsigned& a0, unsigned& a1, unsigned& a2, unsigned& a3,
                                        unsigned addr) {
    asm volatile("ldmatrix.sync.aligned.m8n8.x4.shared.b16 {%0,%1,%2,%3}, [%4];"
                 : "=r"(a0), "=r"(a1), "=r"(a2), "=r"(a3) : "r"(addr));
}
__device__ __forceinline__ void ldsm_x4t(unsigned& a0, unsigned& a1, unsigned& a2, unsigned& a3,
                                         unsigned addr) {
    asm volatile("ldmatrix.sync.aligned.m8n8.x4.trans.shared.b16 {%0,%1,%2,%3}, [%4];"
                 : "=r"(a0), "=r"(a1), "=r"(a2), "=r"(a3) : "r"(addr));
}
__device__ __forceinline__ void ldsm_x2t(unsigned& b0, unsigned& b1, unsigned addr) {
    asm volatile("ldmatrix.sync.aligned.m8n8.x2.trans.shared.b16 {%0,%1}, [%2];"
                 : "=r"(b0), "=r"(b1) : "r"(addr));
}
__device__ __forceinline__ void ldsm_x1t(unsigned& b0, unsigned addr) {
    asm volatile("ldmatrix.sync.aligned.m8n8.x1.trans.shared.b16 {%0}, [%1];"
                 : "=r"(b0) : "r"(addr));
}
__device__ __forceinline__ unsigned s2u(const void* p) {
    return (unsigned)__cvta_generic_to_shared(p);
}

__global__ void prep_kernel(const float* __restrict__ qkv_w, const float* __restrict__ qkv_b,
                            const float* __restrict__ proj_w,
                            const float* __restrict__ bias_table, const int* __restrict__ rel_index) {
    const float SC = 0.17677669529663687f;
    int i = blockIdx.x * 256 + threadIdx.x;
    if (i < 6 * QKVC * 4) {
        int kk = i / (QKVC * 4), rem = i % (QKVC * 4), c = rem >> 2, tg = rem & 3;
        float s = (c < DIM) ? SC : 1.0f;
        int k0 = kk * 16 + 2 * tg;
        half2 lo = __floats2half2_rn(qkv_w[k0 * QKVC + c] * s, qkv_w[(k0 + 1) * QKVC + c] * s);
        half2 hi = __floats2half2_rn(qkv_w[(k0 + 8) * QKVC + c] * s, qkv_w[(k0 + 9) * QKVC + c] * s);
        g_wq[i] = make_uint2(*(unsigned*)&lo, *(unsigned*)&hi);
    }
    if (i < 6 * DIM * 4) {
        int kk = i / (DIM * 4), rem = i % (DIM * 4), c = rem >> 2, tg = rem & 3;
        int k0 = kk * 16 + 2 * tg;
        half2 lo = __floats2half2_rn(proj_w[k0 * DIM + c], proj_w[(k0 + 1) * DIM + c]);
        half2 hi = __floats2half2_rn(proj_w[(k0 + 8) * DIM + c], proj_w[(k0 + 9) * DIM + c]);
        g_wp[i] = make_uint2(*(unsigned*)&lo, *(unsigned*)&hi);
    }
    if (i < QKVC) g_qb[i] = qkv_b[i] * ((i < DIM) ? SC : 1.0f);
    if (i < 3 * 64 * 28) {
        int h = i / (64 * 28), rem = i % (64 * 28), m = rem / 28, p = rem % 28;
        int n0 = 2 * p, n1 = 2 * p + 1;
        float b0 = (m < NTOK && n0 < NTOK) ? bias_table[rel_index[m * NTOK + n0] * 3 + h] : 0.f;
        float b1 = (m < NTOK && n1 < NTOK) ? bias_table[rel_index[m * NTOK + n1] * 3 + h] : 0.f;
        half2 hb = __floats2half2_rn(b0, b1);
        g_biash[i] = *(unsigned*)&hb;
    }
}

__global__ void __launch_bounds__(384, 2)
win_attn_kernel(const float* __restrict__ x,
                const float* __restrict__ proj_b,
                float*       __restrict__ out)
{
    extern __shared__ __half smh[];
    __half* qk = smh;                  // [64][296]; reused as f32 staging in stage 5
    __half* xo = smh + QKV_HALVES;     // [64][104] x tile, then O
    float*  os = (float*)smh;          // stage-5 staging [49][104] f32 (aliases qk)

    const int b    = blockIdx.x;
    const int tid  = threadIdx.x;
    const int warp = tid >> 5;           // 0..11
    const int lane = tid & 31;
    const int g    = lane >> 2;
    const int tg   = lane & 3;
    const int rl   = lane & 7;
    const int sel  = lane >> 3;
    const float NEGINF = __int_as_float(0xff800000);

    const unsigned qk_u = s2u(qk);
    const unsigned xo_u = s2u(xo);

    const int rowA  = (sel & 1) << 3;        // ldsm A row offset
    const int colAh = (sel >> 1) << 3;       // ldsm A col offset (halves)

    // ---- stage 0: x (fp16) -> xo; zero qk pad rows 49..63 ----
    const float* xg = x + (size_t)b * (NTOK * DIM);
    for (int i = tid; i < NTOK * DIM / 4; i += 384) {
        int n = i / (DIM / 4), k4 = i % (DIM / 4);
        float4 v = ((const float4*)xg)[i];
        *(uint2*)&xo[n * XO_ST + 4 * k4] = make_uint2(pkh(v.x, v.y), pkh(v.z, v.w));
    }
    {
        uint2* zp = (uint2*)&qk[49 * QKV_ST];
        for (int i = tid; i < 15 * QKV_ST / 4; i += 384) zp[i] = make_uint2(0u, 0u);
    }
    __syncthreads();

    // ---- stage 1: qkv = x @ Wqkv + b. 12 warps x (4 m-tiles x 24 cols) ----
    {
        const int cbase = warp * 24;

        unsigned aaddr[4];
        #pragma unroll
        for (int mt = 0; mt < 4; mt++)
            aaddr[mt] = xo_u + (((mt * 16 + rl + rowA) * XO_ST + colAh) << 1);

        float acc[4][3][4];
        #pragma unroll
        for (int mt = 0; mt < 4; mt++)
            #pragma unroll
            for (int ni = 0; ni < 3; ni++)
                #pragma unroll
                for (int j = 0; j < 4; j++) acc[mt][ni][j] = 0.f;

        const uint2* wq = &g_wq[(cbase + g) * 4 + tg];
        uint2 Bc[3];
        #pragma unroll
        for (int ni = 0; ni < 3; ni++) Bc[ni] = wq[ni * 32];
        wq += QKVC * 4;

        #pragma unroll 1
        for (int kk = 0; kk < 6; kk++) {
            unsigned A[4][4];
            #pragma unroll
            for (int mt = 0; mt < 4; mt++) {
                ldsm_x4(A[mt][0], A[mt][1], A[mt][2], A[mt][3], aaddr[mt]);
                aaddr[mt] += 32;          // +16 halves
            }
            uint2 Bn[3];
            if (kk < 5) {
                #pragma unroll
                for (int ni = 0; ni < 3; ni++) Bn[ni] = wq[ni * 32];
                wq += QKVC * 4;
            }
            #pragma unroll
            for (int mt = 0; mt < 4; mt++)
                #pragma unroll
                for (int ni = 0; ni < 3; ni++)
                    mma16(acc[mt][ni][0], acc[mt][ni][1], acc[mt][ni][2], acc[mt][ni][3],
                          A[mt][0], A[mt][1], A[mt][2], A[mt][3], Bc[ni].x, Bc[ni].y);
            #pragma unroll
            for (int ni = 0; ni < 3; ni++) Bc[ni] = Bn[ni];
        }

        #pragma unroll
        for (int ni = 0; ni < 3; ni++) {
            int col = cbase + ni * 8 + tg * 2;
            float2 bb = *(const float2*)&g_qb[col];
            #pragma unroll
            for (int mt = 0; mt < 4; mt++) {
                int rA = mt * 16 + g, rB = rA + 8;
                if (rA < NTOK) *(unsigned*)&qk[rA * QKV_ST + col] =
                    pkh(acc[mt][ni][0] + bb.x, acc[mt][ni][1] + bb.y);
                if (rB < NTOK) *(unsigned*)&qk[rB * QKV_ST + col] =
                    pkh(acc[mt][ni][2] + bb.x, acc[mt][ni][3] + bb.y);
            }
        }
    }
    __syncthreads();

    // ---- stages 2-4 fused: 12 jobs = (h, mt); P never touches smem ----
    {
        const int h = warp >> 2, mt = warp & 3, m0 = mt * 16;
        const int rA = m0 + g, rB = rA + 8;

        // S = Qs @ K^T
        float a[7][4];
        #pragma unroll
        for (int nt = 0; nt < 7; nt++)
            #pragma unroll
            for (int j = 0; j < 4; j++) a[nt][j] = 0.f;

        unsigned Aq[2][4];
        {
            unsigned qaddr = qk_u + (((m0 + rl + rowA) * QKV_ST + h * 32 + colAh) << 1);
            ldsm_x4(Aq[0][0], Aq[0][1], Aq[0][2], Aq[0][3], qaddr);
            ldsm_x4(Aq[1][0], Aq[1][1], Aq[1][2], Aq[1][3], qaddr + 32);
        }
        {
            unsigned kaddr = qk_u + ((rl * QKV_ST + 96 + h * 32 + (sel << 3)) << 1);
            #pragma unroll
            for (int nt = 0; nt < 7; nt++) {
                unsigned b0, b1, b2, b3;
                ldsm_x4(b0, b1, b2, b3, kaddr);
                kaddr += (8 * QKV_ST) << 1;
                mma16(a[nt][0], a[nt][1], a[nt][2], a[nt][3],
                      Aq[0][0], Aq[0][1], Aq[0][2], Aq[0][3], b0, b1);
                mma16(a[nt][0], a[nt][1], a[nt][2], a[nt][3],
                      Aq[1][0], Aq[1][1], Aq[1][2], Aq[1][3], b2, b3);
            }
        }

        // + bias (half2), -inf mask on pad cols
        const unsigned* bpA = &g_biash[(h * 64 + rA) * 28 + tg];
        const unsigned* bpB = &g_biash[(h * 64 + rB) * 28 + tg];
        #pragma unroll
        for (int nt = 0; nt < 7; nt++) {
            int n0p = nt * 8 + tg * 2;
            float2 bA = uph(bpA[nt * 4]);
            float2 bB = uph(bpB[nt * 4]);
            a[nt][0] = (n0p     < NTOK) ? a[nt][0] + bA.x : NEGINF;
            a[nt][1] = (n0p + 1 < NTOK) ? a[nt][1] + bA.y : NEGINF;
            a[nt][2] = (n0p     < NTOK) ? a[nt][2] + bB.x : NEGINF;
            a[nt][3] = (n0p + 1 < NTOK) ? a[nt][3] + bB.y : NEGINF;
        }

        // register softmax
        float mA = NEGINF, mB = NEGINF;
        #pragma unroll
        for (int nt = 0; nt < 7; nt++) {
            mA = fmaxf(mA, fmaxf(a[nt][0], a[nt][1]));
            mB = fmaxf(mB, fmaxf(a[nt][2], a[nt][3]));
        }
        mA = fmaxf(mA, __shfl_xor_sync(0xffffffffu, mA, 1));
        mA = fmaxf(mA, __shfl_xor_sync(0xffffffffu, mA, 2));
        mB = fmaxf(mB, __shfl_xor_sync(0xffffffffu, mB, 1));
        mB = fmaxf(mB, __shfl_xor_sync(0xffffffffu, mB, 2));
        float sA = 0.f, sB = 0.f;
        #pragma unroll
        for (int nt = 0; nt < 7; nt++) {
            a[nt][0] = __expf(a[nt][0] - mA);
            a[nt][1] = __expf(a[nt][1] - mA);
            a[nt][2] = __expf(a[nt][2] - mB);
            a[nt][3] = __expf(a[nt][3] - mB);
            sA += a[nt][0] + a[nt][1];
            sB += a[nt][2] + a[nt][3];
        }
        sA += __shfl_xor_sync(0xffffffffu, sA, 1);
        sA += __shfl_xor_sync(0xffffffffu, sA, 2);
        sB += __shfl_xor_sync(0xffffffffu, sB, 1);
        sB += __shfl_xor_sync(0xffffffffu, sB, 2);
        float iA = 1.0f / sA, iB = 1.0f / sB;

        // pack P into fp16 A-fragments (C-frag layout == A-frag layout)
        unsigned pa[7][2];
        #pragma unroll
        for (int nt = 0; nt < 7; nt++) {
            pa[nt][0] = pkh(a[nt][0] * iA, a[nt][1] * iA);
            pa[nt][1] = pkh(a[nt][2] * iB, a[nt][3] * iB);
        }

        // O = P @ V  (V via trans B-fragments from [token][dim])
        float o[4][4];
        #pragma unroll
        for (int nt = 0; nt < 4; nt++)
            #pragma unroll
            for (int j = 0; j < 4; j++) o[nt][j] = 0.f;

        #pragma unroll
        for (int nt = 0; nt < 4; nt++) {
            const int vcol = 192 + h * 32 + nt * 8;
            unsigned b0, b1, b2, b3, c0, c1, d0;
            ldsm_x4t(b0, b1, b2, b3, qk_u + (((rl + (sel << 3)) * QKV_ST + vcol) << 1));
            ldsm_x2t(c0, c1, qk_u + (((32 + rl + ((sel & 1) << 3)) * QKV_ST + vcol) << 1));
            ldsm_x1t(d0, qk_u + (((48 + rl) * QKV_ST + vcol) << 1));
            mma16(o[nt][0], o[nt][1], o[nt][2], o[nt][3],
                  pa[0][0], pa[0][1], pa[1][0], pa[1][1], b0, b1);
            mma16(o[nt][0], o[nt][1], o[nt][2], o[nt][3],
                  pa[2][0], pa[2][1], pa[3][0], pa[3][1], b2, b3);
            mma16(o[nt][0], o[nt][1], o[nt][2], o[nt][3],
                  pa[4][0], pa[4][1], pa[5][0], pa[5][1], c0, c1);
            mma8(o[nt][0], o[nt][1], o[nt][2], o[nt][3],
                 pa[6][0], pa[6][1], d0);
        }
        #pragma unroll
        for (int nt = 0; nt < 4; nt++) {
            int col = h * 32 + nt * 8 + tg * 2;
            if (rA < NTOK) *(unsigned*)&xo[rA * XO_ST + col] = pkh(o[nt][0], o[nt][1]);
            if (rB < NTOK) *(unsigned*)&xo[rB * XO_ST + col] = pkh(o[nt][2], o[nt][3]);
        }
    }
    __syncthreads();

    // ---- stage 5: out = O @ Wproj + b -> f32 staging (qk region), then coalesced copy ----
    {
        const int mt = warp & 3, cg = warp >> 2;
        const int m0 = mt * 16, nc0 = cg * 32;
        const int rA = m0 + g, rB = rA + 8;

        float acc[4][4];
        #pragma unroll
        for (int ni = 0; ni < 4; ni++)
            #pragma unroll
            for (int j = 0; j < 4; j++) acc[ni][j] = 0.f;

        unsigned aaddr = xo_u + (((m0 + rl + rowA) * XO_ST + colAh) << 1);
        const uint2* wp = &g_wp[(nc0 + g) * 4 + tg];
        uint2 Bc[4];
        #pragma unroll
        for (int ni = 0; ni < 4; ni++) Bc[ni] = wp[ni * 32];
        wp += DIM * 4;

        #pragma unroll 1
        for (int kk = 0; kk < 6; kk++) {
            unsigned A0, A1, A2, A3;
            ldsm_x4(A0, A1, A2, A3, aaddr); aaddr += 32;
            uint2 Bn[4];
            if (kk < 5) {
                #pragma unroll
                for (int ni = 0; ni < 4; ni++) Bn[ni] = wp[ni * 32];
                wp += DIM * 4;
            }
            #pragma unroll
            for (int ni = 0; ni < 4; ni++)
                mma16(acc[ni][0], acc[ni][1], acc[ni][2], acc[ni][3],
                      A0, A1, A2, A3, Bc[ni].x, Bc[ni].y);
            #pragma unroll
            for (int ni = 0; ni < 4; ni++) Bc[ni] = Bn[ni];
        }

        #pragma unroll
        for (int ni = 0; ni < 4; ni++) {
            int n = nc0 + ni * 8 + tg * 2;
            float2 pb = *(const float2*)&proj_b[n];
            if (rA < NTOK) *(float2*)&os[rA * OS_ST + n] =
                make_float2(acc[ni][0] + pb.x, acc[ni][1] + pb.y);
            if (rB < NTOK) *(float2*)&os[rB * OS_ST + n] =
                make_float2(acc[ni][2] + pb.x, acc[ni][3] + pb.y);
        }
    }
    __syncthreads();

    // coalesced copy-out: [49][96] f32
    {
        float* og = out + (size_t)b * (NTOK * DIM);
        for (int i = tid; i < NTOK * DIM / 4; i += 384) {
            int r = i / 24, c4 = i % 24;
            float4 v = *(float4*)&os[r * OS_ST + c4 * 4];
            *(float4*)&og[r * DIM + c4 * 4] = v;
        }
    }
}

extern "C" void kernel_launch(void* const* d_in, const int* in_sizes, int n_in,
                              void* d_out, int out_size)
{
    const float* x          = (const float*)d_in[0];
    const float* qkv_w      = (const float*)d_in[2];
    const float* qkv_b      = (const float*)d_in[3];
    const float* proj_w     = (const float*)d_in[4];
    const float* proj_b     = (const float*)d_in[5];
    const float* bias_table = (const float*)d_in[6];
    const int*   rel_index  = (const int*)d_in[7];
    float* out = (float*)d_out;

    int nwin = in_sizes[0] / (NTOK * DIM);

    prep_kernel<<<42, 256>>>(qkv_w, qkv_b, proj_w, bias_table, rel_index);

    cudaFuncSetAttribute(win_attn_kernel,
                         cudaFuncAttributeMaxDynamicSharedMemorySize, SMEM_BYTES);
    win_attn_kernel<<<nwin, 384, SMEM_BYTES>>>(x, proj_b, out);
    (void)n_in; (void)out_size;
}

// round 11
// speedup vs baseline: 2.2268x; 1.0133x over previous
#include <cuda_runtime.h>
#include <cuda_fp16.h>
#include <math.h>

#define NTOK 49
#define DIM  96
#define QKVC 288

// ---- shared memory (halves) ----
constexpr int QKV_ST = 296;                    // qk rows 64: Q 0..95 | K 96..191 | V 192..287
constexpr int QKV_HALVES = 64 * QKV_ST;        // 18944
constexpr int XO_ST  = 104;                    // x tile then O, rows 64
constexpr int XO_HALVES = 64 * XO_ST;          // 6656
constexpr int SMEM_BYTES = (QKV_HALVES + XO_HALVES) * 2;   // 51200 -> 2 CTAs/SM
constexpr int OS_ST = 104;                     // f32 output staging stride (aliases qk region)

// ---- precomputed fp16 weights (uint4 = 2 k16-steps) + fused bias (half2) ----
__device__ uint4 g_wq4[3 * QKVC * 4];   // [kkp][col][tg]: {kkA.lo,kkA.hi,kkB.lo,kkB.hi}
__device__ uint4 g_wp4[3 * DIM * 4];
__device__ float g_qb[QKVC];            // qkv bias (q-scaled)
__device__ unsigned g_biash[3 * 64 * 28];   // half2 pairs: [h][m][pair]

__device__ __forceinline__ unsigned pkh(float x, float y) {
    half2 h = __floats2half2_rn(x, y);
    return *(unsigned*)&h;
}
__device__ __forceinline__ float2 uph(unsigned u) {
    return __half22float2(*(half2*)&u);
}
__device__ __forceinline__ void mma16(float& c0, float& c1, float& c2, float& c3,
                                      unsigned a0, unsigned a1, unsigned a2, unsigned a3,
                                      unsigned b0, unsigned b1) {
    asm volatile("mma.sync.aligned.m16n8k16.row.col.f32.f16.f16.f32 "
                 "{%0,%1,%2,%3}, {%4,%5,%6,%7}, {%8,%9}, {%0,%1,%2,%3};"
                 : "+f"(c0), "+f"(c1), "+f"(c2), "+f"(c3)
                 : "r"(a0), "r"(a1), "r"(a2), "r"(a3), "r"(b0), "r"(b1));
}
__device__ __forceinline__ void mma8(float& c0, float& c1, float& c2, float& c3,
                                     unsigned a0, unsigned a1, unsigned b0) {
    asm volatile("mma.sync.aligned.m16n8k8.row.col.f32.f16.f16.f32 "
                 "{%0,%1,%2,%3}, {%4,%5}, {%6}, {%0,%1,%2,%3};"
                 : "+f"(c0), "+f"(c1), "+f"(c2), "+f"(c3)
                 : "r"(a0), "r"(a1), "r"(b0));
}
__device__ __forceinline__ void ldsm_x4(unsigned& a0, unsigned& a1, unsigned& a2, unsigned& a3,
                                        unsigned addr) {
    asm volatile("ldmatrix.sync.aligned.m8n8.x4.shared.b16 {%0,%1,%2,%3}, [%4];"
                 : "=r"(a0), "=r"(a1), "=r"(a2), "=r"(a3) : "r"(addr));
}
__device__ __forceinline__ void ldsm_x4t(unsigned& a0, unsigned& a1, unsigned& a2, unsigned& a3,
                                         unsigned addr) {
    asm volatile("ldmatrix.sync.aligned.m8n8.x4.trans.shared.b16 {%0,%1,%2,%3}, [%4];"
                 : "=r"(a0), "=r"(a1), "=r"(a2), "=r"(a3) : "r"(addr));
}
__device__ __forceinline__ void ldsm_x2t(unsigned& b0, unsigned& b1, unsigned addr) {
    asm volatile("ldmatrix.sync.aligned.m8n8.x2.trans.shared.b16 {%0,%1}, [%2];"
                 : "=r"(b0), "=r"(b1) : "r"(addr));
}
__device__ __forceinline__ void ldsm_x1t(unsigned& b0, unsigned addr) {
    asm volatile("ldmatrix.sync.aligned.m8n8.x1.trans.shared.b16 {%0}, [%1];"
                 : "=r"(b0) : "r"(addr));
}
__device__ __forceinline__ unsigned s2u(const void* p) {
    return (unsigned)__cvta_generic_to_shared(p);
}

__global__ void prep_kernel(const float* __restrict__ qkv_w, const float* __restrict__ qkv_b,
                            const float* __restrict__ proj_w,
                            const float* __restrict__ bias_table, const int* __restrict__ rel_index) {
    const float SC = 0.17677669529663687f;
    int i = blockIdx.x * 256 + threadIdx.x;
    if (i < 3 * QKVC * 4) {
        int kkp = i / (QKVC * 4), rem = i % (QKVC * 4), c = rem >> 2, tg = rem & 3;
        float s = (c < DIM) ? SC : 1.0f;
        int k0 = kkp * 32 + 2 * tg;
        g_wq4[i] = make_uint4(
            pkh(qkv_w[k0 * QKVC + c] * s,        qkv_w[(k0 + 1) * QKVC + c] * s),
            pkh(qkv_w[(k0 + 8) * QKVC + c] * s,  qkv_w[(k0 + 9) * QKVC + c] * s),
            pkh(qkv_w[(k0 + 16) * QKVC + c] * s, qkv_w[(k0 + 17) * QKVC + c] * s),
            pkh(qkv_w[(k0 + 24) * QKVC + c] * s, qkv_w[(k0 + 25) * QKVC + c] * s));
    }
    if (i < 3 * DIM * 4) {
        int kkp = i / (DIM * 4), rem = i % (DIM * 4), c = rem >> 2, tg = rem & 3;
        int k0 = kkp * 32 + 2 * tg;
        g_wp4[i] = make_uint4(
            pkh(proj_w[k0 * DIM + c],        proj_w[(k0 + 1) * DIM + c]),
            pkh(proj_w[(k0 + 8) * DIM + c],  proj_w[(k0 + 9) * DIM + c]),
            pkh(proj_w[(k0 + 16) * DIM + c], proj_w[(k0 + 17) * DIM + c]),
            pkh(proj_w[(k0 + 24) * DIM + c], proj_w[(k0 + 25) * DIM + c]));
    }
    if (i < QKVC) g_qb[i] = qkv_b[i] * ((i < DIM) ? SC : 1.0f);
    if (i < 3 * 64 * 28) {
        int h = i / (64 * 28), rem = i % (64 * 28), m = rem / 28, p = rem % 28;
        int n0 = 2 * p, n1 = 2 * p + 1;
        float b0 = (m < NTOK && n0 < NTOK) ? bias_table[rel_index[m * NTOK + n0] * 3 + h] : 0.f;
        float b1 = (m < NTOK && n1 < NTOK) ? bias_table[rel_index[m * NTOK + n1] * 3 + h] : 0.f;
        g_biash[i] = pkh(b0, b1);
    }
}

__global__ void __launch_bounds__(384, 2)
win_attn_kernel(const float* __restrict__ x,
                const float* __restrict__ proj_b,
                float*       __restrict__ out)
{
    extern __shared__ __half smh[];
    __half* qk = smh;                  // [64][296]; reused as f32 staging in stage 5
    __half* xo = smh + QKV_HALVES;     // [64][104] x tile, then O
    float*  os = (float*)smh;          // stage-5 staging [49][104] f32 (aliases qk)

    const int b    = blockIdx.x;
    const int tid  = threadIdx.x;
    const int warp = tid >> 5;           // 0..11
    const int lane = tid & 31;
    const int g    = lane >> 2;
    const int tg   = lane & 3;
    const int rl   = lane & 7;
    const int sel  = lane >> 3;
    const float NEGINF = __int_as_float(0xff800000);

    const unsigned qk_u = s2u(qk);
    const unsigned xo_u = s2u(xo);

    const int rowA  = (sel & 1) << 3;        // ldsm A row offset
    const int colAh = (sel >> 1) << 3;       // ldsm A col offset (halves)

    // ---- stage 0: x (fp16) -> xo; zero only the V pad region (rows 49..63, cols 192..287) ----
    const float* xg = x + (size_t)b * (NTOK * DIM);
    for (int i = tid; i < NTOK * DIM / 4; i += 384) {
        int n = i / (DIM / 4), k4 = i % (DIM / 4);
        float4 v = ((const float4*)xg)[i];
        *(uint2*)&xo[n * XO_ST + 4 * k4] = make_uint2(pkh(v.x, v.y), pkh(v.z, v.w));
    }
    if (tid < 360) {
        int r = 49 + tid / 24, c = 192 + (tid % 24) * 4;
        *(uint2*)&qk[r * QKV_ST + c] = make_uint2(0u, 0u);
    }
    __syncthreads();

    // ---- stage 1: qkv = x @ Wqkv + b. 12 warps x (4 m-tiles x 24 cols) ----
    {
        const int cbase = warp * 24;

        unsigned aaddr[4];
        #pragma unroll
        for (int mt = 0; mt < 4; mt++)
            aaddr[mt] = xo_u + (((mt * 16 + rl + rowA) * XO_ST + colAh) << 1);

        float acc[4][3][4];
        #pragma unroll
        for (int mt = 0; mt < 4; mt++)
            #pragma unroll
            for (int ni = 0; ni < 3; ni++)
                #pragma unroll
                for (int j = 0; j < 4; j++) acc[mt][ni][j] = 0.f;

        const uint4* wq = &g_wq4[(cbase + g) * 4 + tg];
        uint4 Bc[3];
        #pragma unroll
        for (int ni = 0; ni < 3; ni++) Bc[ni] = wq[ni * 32];
        wq += QKVC * 4;

        #pragma unroll 1
        for (int kkp = 0; kkp < 3; kkp++) {
            unsigned A[4][4];
            #pragma unroll
            for (int mt = 0; mt < 4; mt++) {
                ldsm_x4(A[mt][0], A[mt][1], A[mt][2], A[mt][3], aaddr[mt]);
                aaddr[mt] += 32;
            }
            #pragma unroll
            for (int mt = 0; mt < 4; mt++)
                #pragma unroll
                for (int ni = 0; ni < 3; ni++)
                    mma16(acc[mt][ni][0], acc[mt][ni][1], acc[mt][ni][2], acc[mt][ni][3],
                          A[mt][0], A[mt][1], A[mt][2], A[mt][3], Bc[ni].x, Bc[ni].y);
            uint4 Bn[3];
            if (kkp < 2) {
                #pragma unroll
                for (int ni = 0; ni < 3; ni++) Bn[ni] = wq[ni * 32];
                wq += QKVC * 4;
            }
            #pragma unroll
            for (int mt = 0; mt < 4; mt++) {
                ldsm_x4(A[mt][0], A[mt][1], A[mt][2], A[mt][3], aaddr[mt]);
                aaddr[mt] += 32;
            }
            #pragma unroll
            for (int mt = 0; mt < 4; mt++)
                #pragma unroll
                for (int ni = 0; ni < 3; ni++)
                    mma16(acc[mt][ni][0], acc[mt][ni][1], acc[mt][ni][2], acc[mt][ni][3],
                          A[mt][0], A[mt][1], A[mt][2], A[mt][3], Bc[ni].z, Bc[ni].w);
            #pragma unroll
            for (int ni = 0; ni < 3; ni++) Bc[ni] = Bn[ni];
        }

        #pragma unroll
        for (int ni = 0; ni < 3; ni++) {
            int col = cbase + ni * 8 + tg * 2;
            float2 bb = *(const float2*)&g_qb[col];
            #pragma unroll
            for (int mt = 0; mt < 4; mt++) {
                int rA = mt * 16 + g, rB = rA + 8;
                if (rA < NTOK) *(unsigned*)&qk[rA * QKV_ST + col] =
                    pkh(acc[mt][ni][0] + bb.x, acc[mt][ni][1] + bb.y);
                if (rB < NTOK) *(unsigned*)&qk[rB * QKV_ST + col] =
                    pkh(acc[mt][ni][2] + bb.x, acc[mt][ni][3] + bb.y);
            }
        }
    }
    __syncthreads();

    // ---- stages 2-4 fused: 12 jobs = (h, mt); P never touches smem ----
    {
        const int h = warp >> 2, mt = warp & 3, m0 = mt * 16;
        const int rA = m0 + g, rB = rA + 8;

        // S accumulators initialized with fused bias (pad entries are 0)
        float a[7][4];
        {
            const unsigned* bpA = &g_biash[(h * 64 + rA) * 28 + tg];
            const unsigned* bpB = &g_biash[(h * 64 + rB) * 28 + tg];
            #pragma unroll
            for (int nt = 0; nt < 7; nt++) {
                float2 bA = uph(bpA[nt * 4]);
                float2 bB = uph(bpB[nt * 4]);
                a[nt][0] = bA.x; a[nt][1] = bA.y;
                a[nt][2] = bB.x; a[nt][3] = bB.y;
            }
        }

        // S = Qs @ K^T (+bias already in C)
        unsigned Aq[2][4];
        {
            unsigned qaddr = qk_u + (((m0 + rl + rowA) * QKV_ST + h * 32 + colAh) << 1);
            ldsm_x4(Aq[0][0], Aq[0][1], Aq[0][2], Aq[0][3], qaddr);
            ldsm_x4(Aq[1][0], Aq[1][1], Aq[1][2], Aq[1][3], qaddr + 32);
        }
        {
            unsigned kaddr = qk_u + ((rl * QKV_ST + 96 + h * 32 + (sel << 3)) << 1);
            #pragma unroll
            for (int nt = 0; nt < 7; nt++) {
                unsigned b0, b1, b2, b3;
                ldsm_x4(b0, b1, b2, b3, kaddr);
                kaddr += (8 * QKV_ST) << 1;
                mma16(a[nt][0], a[nt][1], a[nt][2], a[nt][3],
                      Aq[0][0], Aq[0][1], Aq[0][2], Aq[0][3], b0, b1);
                mma16(a[nt][0], a[nt][1], a[nt][2], a[nt][3],
                      Aq[1][0], Aq[1][1], Aq[1][2], Aq[1][3], b2, b3);
            }
        }

        // static pad mask: only tile nt=6 (cols 48..55) has cols >= 49
        if (tg != 0) { a[6][0] = NEGINF; a[6][2] = NEGINF; }
        a[6][1] = NEGINF; a[6][3] = NEGINF;

        // register softmax
        float mA = NEGINF, mB = NEGINF;
        #pragma unroll
        for (int nt = 0; nt < 7; nt++) {
            mA = fmaxf(mA, fmaxf(a[nt][0], a[nt][1]));
            mB = fmaxf(mB, fmaxf(a[nt][2], a[nt][3]));
        }
        mA = fmaxf(mA, __shfl_xor_sync(0xffffffffu, mA, 1));
        mA = fmaxf(mA, __shfl_xor_sync(0xffffffffu, mA, 2));
        mB = fmaxf(mB, __shfl_xor_sync(0xffffffffu, mB, 1));
        mB = fmaxf(mB, __shfl_xor_sync(0xffffffffu, mB, 2));
        float sA = 0.f, sB = 0.f;
        #pragma unroll
        for (int nt = 0; nt < 7; nt++) {
            a[nt][0] = __expf(a[nt][0] - mA);
            a[nt][1] = __expf(a[nt][1] - mA);
            a[nt][2] = __expf(a[nt][2] - mB);
            a[nt][3] = __expf(a[nt][3] - mB);
            sA += a[nt][0] + a[nt][1];
            sB += a[nt][2] + a[nt][3];
        }
        sA += __shfl_xor_sync(0xffffffffu, sA, 1);
        sA += __shfl_xor_sync(0xffffffffu, sA, 2);
        sB += __shfl_xor_sync(0xffffffffu, sB, 1);
        sB += __shfl_xor_sync(0xffffffffu, sB, 2);
        float iA = 1.0f / sA, iB = 1.0f / sB;

        // pack P into fp16 A-fragments (C-frag layout == A-frag layout)
        unsigned pa[7][2];
        #pragma unroll
        for (int nt = 0; nt < 7; nt++) {
            pa[nt][0] = pkh(a[nt][0] * iA, a[nt][1] * iA);
            pa[nt][1] = pkh(a[nt][2] * iB, a[nt][3] * iB);
        }

        // O = P @ V  (V via trans B-fragments from [token][dim])
        float o[4][4];
        #pragma unroll
        for (int nt = 0; nt < 4; nt++)
            #pragma unroll
            for (int j = 0; j < 4; j++) o[nt][j] = 0.f;

        #pragma unroll
        for (int nt = 0; nt < 4; nt++) {
            const int vcol = 192 + h * 32 + nt * 8;
            unsigned b0, b1, b2, b3, c0, c1, d0;
            ldsm_x4t(b0, b1, b2, b3, qk_u + (((rl + (sel << 3)) * QKV_ST + vcol) << 1));
            ldsm_x2t(c0, c1, qk_u + (((32 + rl + ((sel & 1) << 3)) * QKV_ST + vcol) << 1));
            ldsm_x1t(d0, qk_u + (((48 + rl) * QKV_ST + vcol) << 1));
            mma16(o[nt][0], o[nt][1], o[nt][2], o[nt][3],
                  pa[0][0], pa[0][1], pa[1][0], pa[1][1], b0, b1);
            mma16(o[nt][0], o[nt][1], o[nt][2], o[nt][3],
                  pa[2][0], pa[2][1], pa[3][0], pa[3][1], b2, b3);
            mma16(o[nt][0], o[nt][1], o[nt][2], o[nt][3],
                  pa[4][0], pa[4][1], pa[5][0], pa[5][1], c0, c1);
            mma8(o[nt][0], o[nt][1], o[nt][2], o[nt][3],
                 pa[6][0], pa[6][1], d0);
        }
        #pragma unroll
        for (int nt = 0; nt < 4; nt++) {
            int col = h * 32 + nt * 8 + tg * 2;
            if (rA < NTOK) *(unsigned*)&xo[rA * XO_ST + col] = pkh(o[nt][0], o[nt][1]);
            if (rB < NTOK) *(unsigned*)&xo[rB * XO_ST + col] = pkh(o[nt][2], o[nt][3]);
        }
    }
    __syncthreads();

    // ---- stage 5: out = O @ Wproj + b -> f32 staging (qk region), then coalesced copy ----
    {
        const int mt = warp & 3, cg = warp >> 2;
        const int m0 = mt * 16, nc0 = cg * 32;
        const int rA = m0 + g, rB = rA + 8;

        float acc[4][4];
        #pragma unroll
        for (int ni = 0; ni < 4; ni++)
            #pragma unroll
            for (int j = 0; j < 4; j++) acc[ni][j] = 0.f;

        unsigned aaddr = xo_u + (((m0 + rl + rowA) * XO_ST + colAh) << 1);
        const uint4* wp = &g_wp4[(nc0 + g) * 4 + tg];
        uint4 Bc[4];
        #pragma unroll
        for (int ni = 0; ni < 4; ni++) Bc[ni] = wp[ni * 32];
        wp += DIM * 4;

        #pragma unroll 1
        for (int kkp = 0; kkp < 3; kkp++) {
            unsigned A0, A1, A2, A3;
            ldsm_x4(A0, A1, A2, A3, aaddr); aaddr += 32;
            #pragma unroll
            for (int ni = 0; ni < 4; ni++)
                mma16(acc[ni][0], acc[ni][1], acc[ni][2], acc[ni][3],
                      A0, A1, A2, A3, Bc[ni].x, Bc[ni].y);
            uint4 Bn[4];
            if (kkp < 2) {
                #pragma unroll
                for (int ni = 0; ni < 4; ni++) Bn[ni] = wp[ni * 32];
                wp += DIM * 4;
            }
            ldsm_x4(A0, A1, A2, A3, aaddr); aaddr += 32;
            #pragma unroll
            for (int ni = 0; ni < 4; ni++)
                mma16(acc[ni][0], acc[ni][1], acc[ni][2], acc[ni][3],
                      A0, A1, A2, A3, Bc[ni].z, Bc[ni].w);
            #pragma unroll
            for (int ni = 0; ni < 4; ni++) Bc[ni] = Bn[ni];
        }

        #pragma unroll
        for (int ni = 0; ni < 4; ni++) {
            int n = nc0 + ni * 8 + tg * 2;
            float2 pb = *(const float2*)&proj_b[n];
            if (rA < NTOK) *(float2*)&os[rA * OS_ST + n] =
                make_float2(acc[ni][0] + pb.x, acc[ni][1] + pb.y);
            if (rB < NTOK) *(float2*)&os[rB * OS_ST + n] =
                make_float2(acc[ni][2] + pb.x, acc[ni][3] + pb.y);
        }
    }
    __syncthreads();

    // coalesced copy-out: [49][96] f32
    {
        float* og = out + (size_t)b * (NTOK * DIM);
        for (int i = tid; i < NTOK * DIM / 4; i += 384) {
            int r = i / 24, c4 = i % 24;
            float4 v = *(float4*)&os[r * OS_ST + c4 * 4];
            *(float4*)&og[r * DIM + c4 * 4] = v;
        }
    }
}

extern "C" void kernel_launch(void* const* d_in, const int* in_sizes, int n_in,
                              void* d_out, int out_size)
{
    const float* x          = (const float*)d_in[0];
    const float* qkv_w      = (const float*)d_in[2];
    const float* qkv_b      = (const float*)d_in[3];
    const float* proj_w     = (const float*)d_in[4];
    const float* proj_b     = (const float*)d_in[5];
    const float* bias_table = (const float*)d_in[6];
    const int*   rel_index  = (const int*)d_in[7];
    float* out = (float*)d_out;

    int nwin = in_sizes[0] / (NTOK * DIM);

    prep_kernel<<<21, 256>>>(qkv_w, qkv_b, proj_w, bias_table, rel_index);

    cudaFuncSetAttribute(win_attn_kernel,
                         cudaFuncAttributeMaxDynamicSharedMemorySize, SMEM_BYTES);
    win_attn_kernel<<<nwin, 384, SMEM_BYTES>>>(x, proj_b, out);
    (void)n_in; (void)out_size;
}

// round 12
// speedup vs baseline: 2.2895x; 1.0281x over previous
#include <cuda_runtime.h>
#include <cuda_fp16.h>
#include <math.h>

#define NTOK 49
#define DIM  96
#define QKVC 288

// ---- shared memory (halves) ----
constexpr int QKV_ST = 296;                    // qk rows 64: Q 0..95 | K 96..191 | V 192..287
constexpr int QKV_HALVES = 64 * QKV_ST;        // 18944
constexpr int XO_ST  = 104;                    // x tile then O, rows 64
constexpr int XO_HALVES = 64 * XO_ST;          // 6656
constexpr int SMEM_BYTES = (QKV_HALVES + XO_HALVES) * 2;   // 51200 -> 2 CTAs/SM
constexpr int OS_ST = 104;                     // f32 output staging stride (aliases qk region)

// ---- precomputed fp16 weights (uint4 = 2 k16-steps) + fragment-major bias ----
__device__ uint4 g_wq4[3 * QKVC * 4];   // [kkp][col][tg]
__device__ uint4 g_wp4[3 * DIM * 4];
__device__ float g_qb[QKVC];            // qkv bias (q-scaled)
__device__ uint2 g_bfrag[12 * 7 * 32];  // [(h*4+mt)][nt][lane] = {half2(rowA), half2(rowB)}

__device__ __forceinline__ unsigned pkh(float x, float y) {
    half2 h = __floats2half2_rn(x, y);
    return *(unsigned*)&h;
}
__device__ __forceinline__ float2 uph(unsigned u) {
    return __half22float2(*(half2*)&u);
}
__device__ __forceinline__ void mma16(float& c0, float& c1, float& c2, float& c3,
                                      unsigned a0, unsigned a1, unsigned a2, unsigned a3,
                                      unsigned b0, unsigned b1) {
    asm volatile("mma.sync.aligned.m16n8k16.row.col.f32.f16.f16.f32 "
                 "{%0,%1,%2,%3}, {%4,%5,%6,%7}, {%8,%9}, {%0,%1,%2,%3};"
                 : "+f"(c0), "+f"(c1), "+f"(c2), "+f"(c3)
                 : "r"(a0), "r"(a1), "r"(a2), "r"(a3), "r"(b0), "r"(b1));
}
__device__ __forceinline__ void mma8(float& c0, float& c1, float& c2, float& c3,
                                     unsigned a0, unsigned a1, unsigned b0) {
    asm volatile("mma.sync.aligned.m16n8k8.row.col.f32.f16.f16.f32 "
                 "{%0,%1,%2,%3}, {%4,%5}, {%6}, {%0,%1,%2,%3};"
                 : "+f"(c0), "+f"(c1), "+f"(c2), "+f"(c3)
                 : "r"(a0), "r"(a1), "r"(b0));
}
__device__ __forceinline__ void ldsm_x4(unsigned& a0, unsigned& a1, unsigned& a2, unsigned& a3,
                                        unsigned addr) {
    asm volatile("ldmatrix.sync.aligned.m8n8.x4.shared.b16 {%0,%1,%2,%3}, [%4];"
                 : "=r"(a0), "=r"(a1), "=r"(a2), "=r"(a3) : "r"(addr));
}
__device__ __forceinline__ void ldsm_x4t(unsigned& a0, unsigned& a1, unsigned& a2, unsigned& a3,
                                         unsigned addr) {
    asm volatile("ldmatrix.sync.aligned.m8n8.x4.trans.shared.b16 {%0,%1,%2,%3}, [%4];"
                 : "=r"(a0), "=r"(a1), "=r"(a2), "=r"(a3) : "r"(addr));
}
__device__ __forceinline__ void ldsm_x2t(unsigned& b0, unsigned& b1, unsigned addr) {
    asm volatile("ldmatrix.sync.aligned.m8n8.x2.trans.shared.b16 {%0,%1}, [%2];"
                 : "=r"(b0), "=r"(b1) : "r"(addr));
}
__device__ __forceinline__ void ldsm_x1t(unsigned& b0, unsigned addr) {
    asm volatile("ldmatrix.sync.aligned.m8n8.x1.trans.shared.b16 {%0}, [%1];"
                 : "=r"(b0) : "r"(addr));
}
__device__ __forceinline__ unsigned s2u(const void* p) {
    return (unsigned)__cvta_generic_to_shared(p);
}

__global__ void prep_kernel(const float* __restrict__ qkv_w, const float* __restrict__ qkv_b,
                            const float* __restrict__ proj_w,
                            const float* __restrict__ bias_table, const int* __restrict__ rel_index) {
    const float SC = 0.17677669529663687f;
    int i = blockIdx.x * 256 + threadIdx.x;
    if (i < 3 * QKVC * 4) {
        int kkp = i / (QKVC * 4), rem = i % (QKVC * 4), c = rem >> 2, tg = rem & 3;
        float s = (c < DIM) ? SC : 1.0f;
        int k0 = kkp * 32 + 2 * tg;
        g_wq4[i] = make_uint4(
            pkh(qkv_w[k0 * QKVC + c] * s,        qkv_w[(k0 + 1) * QKVC + c] * s),
            pkh(qkv_w[(k0 + 8) * QKVC + c] * s,  qkv_w[(k0 + 9) * QKVC + c] * s),
            pkh(qkv_w[(k0 + 16) * QKVC + c] * s, qkv_w[(k0 + 17) * QKVC + c] * s),
            pkh(qkv_w[(k0 + 24) * QKVC + c] * s, qkv_w[(k0 + 25) * QKVC + c] * s));
    }
    if (i < 3 * DIM * 4) {
        int kkp = i / (DIM * 4), rem = i % (DIM * 4), c = rem >> 2, tg = rem & 3;
        int k0 = kkp * 32 + 2 * tg;
        g_wp4[i] = make_uint4(
            pkh(proj_w[k0 * DIM + c],        proj_w[(k0 + 1) * DIM + c]),
            pkh(proj_w[(k0 + 8) * DIM + c],  proj_w[(k0 + 9) * DIM + c]),
            pkh(proj_w[(k0 + 16) * DIM + c], proj_w[(k0 + 17) * DIM + c]),
            pkh(proj_w[(k0 + 24) * DIM + c], proj_w[(k0 + 25) * DIM + c]));
    }
    if (i < QKVC) g_qb[i] = qkv_b[i] * ((i < DIM) ? SC : 1.0f);
    if (i < 12 * 7 * 32) {
        int job = i / (7 * 32), rem = i % (7 * 32), nt = rem / 32, lane = rem % 32;
        int h = job >> 2, mt = job & 3;
        int g = lane >> 2, tg = lane & 3;
        int rA = mt * 16 + g, rB = rA + 8;
        int n0 = nt * 8 + tg * 2, n1 = n0 + 1;
        float a0 = (rA < NTOK && n0 < NTOK) ? bias_table[rel_index[rA * NTOK + n0] * 3 + h] : 0.f;
        float a1 = (rA < NTOK && n1 < NTOK) ? bias_table[rel_index[rA * NTOK + n1] * 3 + h] : 0.f;
        float b0 = (rB < NTOK && n0 < NTOK) ? bias_table[rel_index[rB * NTOK + n0] * 3 + h] : 0.f;
        float b1 = (rB < NTOK && n1 < NTOK) ? bias_table[rel_index[rB * NTOK + n1] * 3 + h] : 0.f;
        g_bfrag[i] = make_uint2(pkh(a0, a1), pkh(b0, b1));
    }
}

__global__ void __launch_bounds__(384, 2)
win_attn_kernel(const float* __restrict__ x,
                const float* __restrict__ proj_b,
                float*       __restrict__ out)
{
    extern __shared__ __half smh[];
    __half* qk = smh;                  // [64][296]; reused as f32 staging in stage 5
    __half* xo = smh + QKV_HALVES;     // [64][104] x tile, then O
    float*  os = (float*)smh;          // stage-5 staging [49][104] f32 (aliases qk)

    const int b    = blockIdx.x;
    const int tid  = threadIdx.x;
    const int warp = tid >> 5;           // 0..11
    const int lane = tid & 31;
    const int g    = lane >> 2;
    const int tg   = lane & 3;
    const int rl   = lane & 7;
    const int sel  = lane >> 3;
    const float NEGINF = __int_as_float(0xff800000);

    const unsigned qk_u = s2u(qk);
    const unsigned xo_u = s2u(xo);

    const int rowA  = (sel & 1) << 3;        // ldsm A row offset
    const int colAh = (sel >> 1) << 3;       // ldsm A col offset (halves)

    // ---- stage 0: x (fp16) -> xo; zero only the V pad region (rows 49..63, cols 192..287) ----
    const float* xg = x + (size_t)b * (NTOK * DIM);
    for (int i = tid; i < NTOK * DIM / 4; i += 384) {
        int n = i / (DIM / 4), k4 = i % (DIM / 4);
        float4 v = ((const float4*)xg)[i];
        *(uint2*)&xo[n * XO_ST + 4 * k4] = make_uint2(pkh(v.x, v.y), pkh(v.z, v.w));
    }
    if (tid < 360) {
        int r = 49 + tid / 24, c = 192 + (tid % 24) * 4;
        *(uint2*)&qk[r * QKV_ST + c] = make_uint2(0u, 0u);
    }
    __syncthreads();

    // ---- stage 1: qkv = x @ Wqkv + b. 12 warps x (4 m-tiles x 24 cols) ----
    {
        const int cbase = warp * 24;

        unsigned aaddr[4];
        #pragma unroll
        for (int mt = 0; mt < 4; mt++)
            aaddr[mt] = xo_u + (((mt * 16 + rl + rowA) * XO_ST + colAh) << 1);

        float acc[4][3][4];
        #pragma unroll
        for (int mt = 0; mt < 4; mt++)
            #pragma unroll
            for (int ni = 0; ni < 3; ni++)
                #pragma unroll
                for (int j = 0; j < 4; j++) acc[mt][ni][j] = 0.f;

        const uint4* wq = &g_wq4[(cbase + g) * 4 + tg];
        uint4 Bc[3];
        #pragma unroll
        for (int ni = 0; ni < 3; ni++) Bc[ni] = wq[ni * 32];
        wq += QKVC * 4;

        #pragma unroll 1
        for (int kkp = 0; kkp < 3; kkp++) {
            unsigned A[4][4];
            #pragma unroll
            for (int mt = 0; mt < 4; mt++) {
                ldsm_x4(A[mt][0], A[mt][1], A[mt][2], A[mt][3], aaddr[mt]);
                aaddr[mt] += 32;
            }
            #pragma unroll
            for (int mt = 0; mt < 4; mt++)
                #pragma unroll
                for (int ni = 0; ni < 3; ni++)
                    mma16(acc[mt][ni][0], acc[mt][ni][1], acc[mt][ni][2], acc[mt][ni][3],
                          A[mt][0], A[mt][1], A[mt][2], A[mt][3], Bc[ni].x, Bc[ni].y);
            uint4 Bn[3];
            if (kkp < 2) {
                #pragma unroll
                for (int ni = 0; ni < 3; ni++) Bn[ni] = wq[ni * 32];
                wq += QKVC * 4;
            }
            #pragma unroll
            for (int mt = 0; mt < 4; mt++) {
                ldsm_x4(A[mt][0], A[mt][1], A[mt][2], A[mt][3], aaddr[mt]);
                aaddr[mt] += 32;
            }
            #pragma unroll
            for (int mt = 0; mt < 4; mt++)
                #pragma unroll
                for (int ni = 0; ni < 3; ni++)
                    mma16(acc[mt][ni][0], acc[mt][ni][1], acc[mt][ni][2], acc[mt][ni][3],
                          A[mt][0], A[mt][1], A[mt][2], A[mt][3], Bc[ni].z, Bc[ni].w);
            #pragma unroll
            for (int ni = 0; ni < 3; ni++) Bc[ni] = Bn[ni];
        }

        #pragma unroll
        for (int ni = 0; ni < 3; ni++) {
            int col = cbase + ni * 8 + tg * 2;
            float2 bb = *(const float2*)&g_qb[col];
            #pragma unroll
            for (int mt = 0; mt < 4; mt++) {
                int rA = mt * 16 + g, rB = rA + 8;
                if (rA < NTOK) *(unsigned*)&qk[rA * QKV_ST + col] =
                    pkh(acc[mt][ni][0] + bb.x, acc[mt][ni][1] + bb.y);
                if (rB < NTOK) *(unsigned*)&qk[rB * QKV_ST + col] =
                    pkh(acc[mt][ni][2] + bb.x, acc[mt][ni][3] + bb.y);
            }
        }
    }
    __syncthreads();

    // ---- stages 2-4 fused: 12 jobs = (h, mt); P never touches smem ----
    {
        const int h = warp >> 2, mt = warp & 3, m0 = mt * 16;
        const int rA = m0 + g, rB = rA + 8;

        // S accumulators initialized with fragment-major fused bias (coalesced LDG.64)
        float a[7][4];
        {
            const uint2* bp = &g_bfrag[warp * (7 * 32) + lane];
            #pragma unroll
            for (int nt = 0; nt < 7; nt++) {
                uint2 u = bp[nt * 32];
                float2 fA = uph(u.x);
                float2 fB = uph(u.y);
                a[nt][0] = fA.x; a[nt][1] = fA.y;
                a[nt][2] = fB.x; a[nt][3] = fB.y;
            }
        }

        // S = Qs @ K^T (+bias already in C)
        unsigned Aq[2][4];
        {
            unsigned qaddr = qk_u + (((m0 + rl + rowA) * QKV_ST + h * 32 + colAh) << 1);
            ldsm_x4(Aq[0][0], Aq[0][1], Aq[0][2], Aq[0][3], qaddr);
            ldsm_x4(Aq[1][0], Aq[1][1], Aq[1][2], Aq[1][3], qaddr + 32);
        }
        {
            unsigned kaddr = qk_u + ((rl * QKV_ST + 96 + h * 32 + (sel << 3)) << 1);
            #pragma unroll
            for (int nt = 0; nt < 7; nt++) {
                unsigned b0, b1, b2, b3;
                ldsm_x4(b0, b1, b2, b3, kaddr);
                kaddr += (8 * QKV_ST) << 1;
                mma16(a[nt][0], a[nt][1], a[nt][2], a[nt][3],
                      Aq[0][0], Aq[0][1], Aq[0][2], Aq[0][3], b0, b1);
                mma16(a[nt][0], a[nt][1], a[nt][2], a[nt][3],
                      Aq[1][0], Aq[1][1], Aq[1][2], Aq[1][3], b2, b3);
            }
        }

        // static pad mask: only tile nt=6 (cols 48..55) has cols >= 49
        if (tg != 0) { a[6][0] = NEGINF; a[6][2] = NEGINF; }
        a[6][1] = NEGINF; a[6][3] = NEGINF;

        // register softmax
        float mA = NEGINF, mB = NEGINF;
        #pragma unroll
        for (int nt = 0; nt < 7; nt++) {
            mA = fmaxf(mA, fmaxf(a[nt][0], a[nt][1]));
            mB = fmaxf(mB, fmaxf(a[nt][2], a[nt][3]));
        }
        mA = fmaxf(mA, __shfl_xor_sync(0xffffffffu, mA, 1));
        mA = fmaxf(mA, __shfl_xor_sync(0xffffffffu, mA, 2));
        mB = fmaxf(mB, __shfl_xor_sync(0xffffffffu, mB, 1));
        mB = fmaxf(mB, __shfl_xor_sync(0xffffffffu, mB, 2));
        float sA = 0.f, sB = 0.f;
        #pragma unroll
        for (int nt = 0; nt < 7; nt++) {
            a[nt][0] = __expf(a[nt][0] - mA);
            a[nt][1] = __expf(a[nt][1] - mA);
            a[nt][2] = __expf(a[nt][2] - mB);
            a[nt][3] = __expf(a[nt][3] - mB);
            sA += a[nt][0] + a[nt][1];
            sB += a[nt][2] + a[nt][3];
        }
        sA += __shfl_xor_sync(0xffffffffu, sA, 1);
        sA += __shfl_xor_sync(0xffffffffu, sA, 2);
        sB += __shfl_xor_sync(0xffffffffu, sB, 1);
        sB += __shfl_xor_sync(0xffffffffu, sB, 2);
        float iA = 1.0f / sA, iB = 1.0f / sB;

        // pack P into fp16 A-fragments (C-frag layout == A-frag layout)
        unsigned pa[7][2];
        #pragma unroll
        for (int nt = 0; nt < 7; nt++) {
            pa[nt][0] = pkh(a[nt][0] * iA, a[nt][1] * iA);
            pa[nt][1] = pkh(a[nt][2] * iB, a[nt][3] * iB);
        }

        // O = P @ V  (V via trans B-fragments from [token][dim])
        float o[4][4];
        #pragma unroll
        for (int nt = 0; nt < 4; nt++)
            #pragma unroll
            for (int j = 0; j < 4; j++) o[nt][j] = 0.f;

        #pragma unroll
        for (int nt = 0; nt < 4; nt++) {
            const int vcol = 192 + h * 32 + nt * 8;
            unsigned b0, b1, b2, b3, c0, c1, d0;
            ldsm_x4t(b0, b1, b2, b3, qk_u + (((rl + (sel << 3)) * QKV_ST + vcol) << 1));
            ldsm_x2t(c0, c1, qk_u + (((32 + rl + ((sel & 1) << 3)) * QKV_ST + vcol) << 1));
            ldsm_x1t(d0, qk_u + (((48 + rl) * QKV_ST + vcol) << 1));
            mma16(o[nt][0], o[nt][1], o[nt][2], o[nt][3],
                  pa[0][0], pa[0][1], pa[1][0], pa[1][1], b0, b1);
            mma16(o[nt][0], o[nt][1], o[nt][2], o[nt][3],
                  pa[2][0], pa[2][1], pa[3][0], pa[3][1], b2, b3);
            mma16(o[nt][0], o[nt][1], o[nt][2], o[nt][3],
                  pa[4][0], pa[4][1], pa[5][0], pa[5][1], c0, c1);
            mma8(o[nt][0], o[nt][1], o[nt][2], o[nt][3],
                 pa[6][0], pa[6][1], d0);
        }
        #pragma unroll
        for (int nt = 0; nt < 4; nt++) {
            int col = h * 32 + nt * 8 + tg * 2;
            if (rA < NTOK) *(unsigned*)&xo[rA * XO_ST + col] = pkh(o[nt][0], o[nt][1]);
            if (rB < NTOK) *(unsigned*)&xo[rB * XO_ST + col] = pkh(o[nt][2], o[nt][3]);
        }
    }
    __syncthreads();

    // ---- stage 5: out = O @ Wproj + b -> f32 staging (qk region), then coalesced copy ----
    {
        const int mt = warp & 3, cg = warp >> 2;
        const int m0 = mt * 16, nc0 = cg * 32;
        const int rA = m0 + g, rB = rA + 8;

        float acc[4][4];
        #pragma unroll
        for (int ni = 0; ni < 4; ni++)
            #pragma unroll
            for (int j = 0; j < 4; j++) acc[ni][j] = 0.f;

        unsigned aaddr = xo_u + (((m0 + rl + rowA) * XO_ST + colAh) << 1);
        const uint4* wp = &g_wp4[(nc0 + g) * 4 + tg];
        uint4 Bc[4];
        #pragma unroll
        for (int ni = 0; ni < 4; ni++) Bc[ni] = wp[ni * 32];
        wp += DIM * 4;

        #pragma unroll 1
        for (int kkp = 0; kkp < 3; kkp++) {
            unsigned A0, A1, A2, A3;
            ldsm_x4(A0, A1, A2, A3, aaddr); aaddr += 32;
            #pragma unroll
            for (int ni = 0; ni < 4; ni++)
                mma16(acc[ni][0], acc[ni][1], acc[ni][2], acc[ni][3],
                      A0, A1, A2, A3, Bc[ni].x, Bc[ni].y);
            uint4 Bn[4];
            if (kkp < 2) {
                #pragma unroll
                for (int ni = 0; ni < 4; ni++) Bn[ni] = wp[ni * 32];
                wp += DIM * 4;
            }
            ldsm_x4(A0, A1, A2, A3, aaddr); aaddr += 32;
            #pragma unroll
            for (int ni = 0; ni < 4; ni++)
                mma16(acc[ni][0], acc[ni][1], acc[ni][2], acc[ni][3],
                      A0, A1, A2, A3, Bc[ni].z, Bc[ni].w);
            #pragma unroll
            for (int ni = 0; ni < 4; ni++) Bc[ni] = Bn[ni];
        }

        #pragma unroll
        for (int ni = 0; ni < 4; ni++) {
            int n = nc0 + ni * 8 + tg * 2;
            float2 pb = *(const float2*)&proj_b[n];
            if (rA < NTOK) *(float2*)&os[rA * OS_ST + n] =
                make_float2(acc[ni][0] + pb.x, acc[ni][1] + pb.y);
            if (rB < NTOK) *(float2*)&os[rB * OS_ST + n] =
                make_float2(acc[ni][2] + pb.x, acc[ni][3] + pb.y);
        }
    }
    __syncthreads();

    // coalesced copy-out: [49][96] f32
    {
        float* og = out + (size_t)b * (NTOK * DIM);
        for (int i = tid; i < NTOK * DIM / 4; i += 384) {
            int r = i / 24, c4 = i % 24;
            float4 v = *(float4*)&os[r * OS_ST + c4 * 4];
            *(float4*)&og[r * DIM + c4 * 4] = v;
        }
    }
}

extern "C" void kernel_launch(void* const* d_in, const int* in_sizes, int n_in,
                              void* d_out, int out_size)
{
    const float* x          = (const float*)d_in[0];
    const float* qkv_w      = (const float*)d_in[2];
    const float* qkv_b      = (const float*)d_in[3];
    const float* proj_w     = (const float*)d_in[4];
    const float* proj_b     = (const float*)d_in[5];
    const float* bias_table = (const float*)d_in[6];
    const int*   rel_index  = (const int*)d_in[7];
    float* out = (float*)d_out;

    int nwin = in_sizes[0] / (NTOK * DIM);

    prep_kernel<<<21, 256>>>(qkv_w, qkv_b, proj_w, bias_table, rel_index);

    cudaFuncSetAttribute(win_attn_kernel,
                         cudaFuncAttributeMaxDynamicSharedMemorySize, SMEM_BYTES);
    win_attn_kernel<<<nwin, 384, SMEM_BYTES>>>(x, proj_b, out);
    (void)n_in; (void)out_size;
}